// round 1
// baseline (speedup 1.0000x reference)
#include <cuda_runtime.h>
#include <math.h>

// Problem constants
static const int NN = 50000;
static const int FF = 64;
static const int HH = 256;
static const int EE = 1600000;
static const int FH = 320;                     // FF + HH
static const int NB_SCAN = (NN + 1023) / 1024; // 49

// ---------------- scratch (__device__ globals; allocation-free) ----------------
__device__ int   d_cnt[NN];
__device__ int   d_rowptr[NN + 1];
__device__ int   d_fill[NN];
__device__ int   d_col[EE];
__device__ int   d_bsum[64];
__device__ float d_deg[NN];
__device__ float d_g1[NN];
__device__ __align__(16) float d_h1 [NN * HH];  // tanh(gin0)
__device__ __align__(16) float d_s  [NN * HH];  // gin1 self+sum agg
__device__ __align__(16) float d_h1b[NN * HH];  // tanh(gin1)
__device__ __align__(16) float d_hcat[NN * FH]; // [x | h1b]
__device__ __align__(16) float d_m0 [NN * FH];  // mean agg of hcat
__device__ __align__(16) float d_h2 [NN * HH];  // relu(sage0)
__device__ __align__(16) float d_m1 [NN * HH];  // mean agg of h2
__device__ __align__(16) float d_h3 [NN * HH];  // relu(sage1)

// ---------------- CSR build ----------------
__global__ void k_zero_cnt() {
    int i = blockIdx.x * blockDim.x + threadIdx.x;
    if (i < NN) d_cnt[i] = 0;
}

__global__ void k_count(const int* __restrict__ dst) {
    int e = blockIdx.x * blockDim.x + threadIdx.x;
    if (e < EE) atomicAdd(&d_cnt[dst[e]], 1);
}

__global__ void k_scan1() {
    __shared__ int sh[1024];
    int tid = threadIdx.x;
    int i = blockIdx.x * 1024 + tid;
    int v = (i < NN) ? d_cnt[i] : 0;
    sh[tid] = v;
    __syncthreads();
#pragma unroll
    for (int off = 1; off < 1024; off <<= 1) {
        int t = (tid >= off) ? sh[tid - off] : 0;
        __syncthreads();
        sh[tid] += t;
        __syncthreads();
    }
    if (i < NN) d_rowptr[i] = sh[tid] - v; // exclusive
    if (tid == 1023) d_bsum[blockIdx.x] = sh[1023];
}

__global__ void k_scan2() {
    if (threadIdx.x == 0 && blockIdx.x == 0) {
        int run = 0;
        for (int b = 0; b < NB_SCAN; b++) {
            int t = d_bsum[b];
            d_bsum[b] = run;
            run += t;
        }
    }
}

__global__ void k_scan3() {
    int i = blockIdx.x * blockDim.x + threadIdx.x;
    if (i < NN) {
        int r = d_rowptr[i] + d_bsum[i >> 10];
        d_rowptr[i] = r;
        d_fill[i] = r;
        float c = (float)d_cnt[i];
        d_deg[i] = fmaxf(c, 1.0f);
    } else if (i == NN) {
        d_rowptr[NN] = EE;
    }
}

__global__ void k_fill(const int* __restrict__ src, const int* __restrict__ dst) {
    int e = blockIdx.x * blockDim.x + threadIdx.x;
    if (e < EE) {
        int pos = atomicAdd(&d_fill[dst[e]], 1);
        d_col[pos] = src[e];
    }
}

// ---------------- GIN0 (K = 1) ----------------
__global__ void k_gin0_agg(const float* __restrict__ x1) {
    int i = blockIdx.x * blockDim.x + threadIdx.x;
    if (i >= NN) return;
    int beg = d_rowptr[i], end = d_rowptr[i + 1];
    float s = x1[i]; // self (eps = 0)
    for (int j = beg; j < end; j++) s += x1[d_col[j]];
    d_g1[i] = s;
}

__global__ void k_gin0_act(const float* __restrict__ w0, const float* __restrict__ b0) {
    int idx = blockIdx.x * blockDim.x + threadIdx.x;
    if (idx >= NN * HH) return;
    int i = idx >> 8;       // / 256
    int c = idx & 255;      // % 256
    d_h1[idx] = tanhf(d_g1[i] * w0[c] + b0[c]);
}

// ---------------- generic aggregation: mode 0 = self+sum (GIN), 1 = mean (SAGE) ----------------
__global__ void k_agg(const float* __restrict__ in, float* __restrict__ out,
                      int D4, int mode) {
    int node = blockIdx.x;
    int t = threadIdx.x; // 64 threads
    int beg = d_rowptr[node], end = d_rowptr[node + 1];
    const float4* in4 = (const float4*)in;
    float4* out4 = (float4*)out;
    bool has1 = (t + 64) < D4; // D4 = 64 (H) or 80 (FH)
    float4 a0 = make_float4(0.f, 0.f, 0.f, 0.f);
    float4 a1 = make_float4(0.f, 0.f, 0.f, 0.f);
    int snext = (beg < end) ? d_col[beg] : 0;
    for (int j = beg; j < end; j++) {
        int s = snext;
        if (j + 1 < end) snext = d_col[j + 1];
        const float4* r = in4 + (long)s * D4;
        float4 v = r[t];
        a0.x += v.x; a0.y += v.y; a0.z += v.z; a0.w += v.w;
        if (has1) {
            float4 w = r[t + 64];
            a1.x += w.x; a1.y += w.y; a1.z += w.z; a1.w += w.w;
        }
    }
    const float4* me = in4 + (long)node * D4;
    if (mode == 0) { // self + sum
        float4 v = me[t];
        a0.x += v.x; a0.y += v.y; a0.z += v.z; a0.w += v.w;
        if (has1) {
            float4 w = me[t + 64];
            a1.x += w.x; a1.y += w.y; a1.z += w.z; a1.w += w.w;
        }
    } else { // mean
        float inv = 1.0f / d_deg[node];
        a0.x *= inv; a0.y *= inv; a0.z *= inv; a0.w *= inv;
        a1.x *= inv; a1.y *= inv; a1.z *= inv; a1.w *= inv;
    }
    out4[(long)node * D4 + t] = a0;
    if (has1) out4[(long)node * D4 + t + 64] = a1;
}

// ---------------- concat [x | h1b] ----------------
__global__ void k_concat(const float* __restrict__ x) {
    int idx = blockIdx.x * blockDim.x + threadIdx.x;
    if (idx >= NN * FH) return;
    int i = idx / FH;
    int c = idx - i * FH;
    d_hcat[idx] = (c < FF) ? x[i * FF + c] : d_h1b[i * HH + (c - FF)];
}

// ---------------- dual-panel fp32 GEMM ----------------
// C[M, 256] = act( A1[M,K1] @ B1[K1,256] + A2[M,K2] @ B2[K2,256] + bias )
// act: 0 none, 1 tanh, 2 relu
__global__ void __launch_bounds__(256, 2)
k_gemm(const float* __restrict__ A1, const float* __restrict__ B1, int K1,
       const float* __restrict__ A2, const float* __restrict__ B2, int K2,
       const float* __restrict__ bias, float* __restrict__ C, int act) {
    const int M = NN, Nc = HH; // output cols fixed = 256
    const int BM = 128, BN = 64, BK = 16;
    __shared__ __align__(16) float As[BK][132]; // padded (stride keeps 16B alignment)
    __shared__ __align__(16) float Bs[BK][BN];

    int tid = threadIdx.x;
    int tx = tid & 15;  // 0..15 -> N dir (x4)
    int ty = tid >> 4;  // 0..15 -> M dir (x8)
    int blockRow = blockIdx.y * BM;
    int blockCol = blockIdx.x * BN;

    float acc[8][4];
#pragma unroll
    for (int m = 0; m < 8; m++)
#pragma unroll
        for (int n = 0; n < 4; n++) acc[m][n] = 0.f;

    int arow = tid >> 2;         // 0..63
    int acol = (tid & 3) * 4;    // 0,4,8,12
    int brow = tid >> 4;         // 0..15
    int bcol = (tid & 15) * 4;   // 0..60

#pragma unroll 1
    for (int pass = 0; pass < 2; pass++) {
        const float* A = pass ? A2 : A1;
        const float* B = pass ? B2 : B1;
        int K = pass ? K2 : K1;
        if (A == nullptr) continue;
#pragma unroll 1
        for (int k0 = 0; k0 < K; k0 += BK) {
            // A tile (transposed into As)
#pragma unroll
            for (int r = 0; r < 2; r++) {
                int row = blockRow + arow + r * 64;
                float4 v = make_float4(0.f, 0.f, 0.f, 0.f);
                if (row < M) v = *(const float4*)&A[(long)row * K + k0 + acol];
                As[acol + 0][arow + r * 64] = v.x;
                As[acol + 1][arow + r * 64] = v.y;
                As[acol + 2][arow + r * 64] = v.z;
                As[acol + 3][arow + r * 64] = v.w;
            }
            // B tile
            *(float4*)&Bs[brow][bcol] =
                *(const float4*)&B[(long)(k0 + brow) * Nc + blockCol + bcol];
            __syncthreads();
#pragma unroll
            for (int k = 0; k < BK; k++) {
                float a[8], b[4];
                *(float4*)&a[0] = *(const float4*)&As[k][ty * 8];
                *(float4*)&a[4] = *(const float4*)&As[k][ty * 8 + 4];
                *(float4*)&b[0] = *(const float4*)&Bs[k][tx * 4];
#pragma unroll
                for (int m = 0; m < 8; m++)
#pragma unroll
                    for (int n = 0; n < 4; n++)
                        acc[m][n] += a[m] * b[n];
            }
            __syncthreads();
        }
    }

    // epilogue
#pragma unroll
    for (int m = 0; m < 8; m++) {
        int row = blockRow + ty * 8 + m;
        if (row >= M) continue;
        int cc = blockCol + tx * 4;
        float4 v;
        v.x = acc[m][0] + bias[cc + 0];
        v.y = acc[m][1] + bias[cc + 1];
        v.z = acc[m][2] + bias[cc + 2];
        v.w = acc[m][3] + bias[cc + 3];
        if (act == 1) {
            v.x = tanhf(v.x); v.y = tanhf(v.y); v.z = tanhf(v.z); v.w = tanhf(v.w);
        } else if (act == 2) {
            v.x = fmaxf(v.x, 0.f); v.y = fmaxf(v.y, 0.f);
            v.z = fmaxf(v.z, 0.f); v.w = fmaxf(v.w, 0.f);
        }
        *(float4*)&C[(long)row * Nc + cc] = v;
    }
}

// ---------------- final linear [N,256] @ [256,2] + b ----------------
__global__ void k_out(const float* __restrict__ h, const float* __restrict__ W,
                      const float* __restrict__ b, float* __restrict__ out) {
    int gwarp = (blockIdx.x * blockDim.x + threadIdx.x) >> 5;
    int lane = threadIdx.x & 31;
    if (gwarp >= NN) return;
    const float* row = h + (long)gwarp * HH;
    float a0 = 0.f, a1 = 0.f;
#pragma unroll
    for (int k = lane; k < HH; k += 32) {
        float v = row[k];
        a0 += v * W[k * 2 + 0];
        a1 += v * W[k * 2 + 1];
    }
#pragma unroll
    for (int o = 16; o > 0; o >>= 1) {
        a0 += __shfl_down_sync(0xFFFFFFFFu, a0, o);
        a1 += __shfl_down_sync(0xFFFFFFFFu, a1, o);
    }
    if (lane == 0) {
        out[gwarp * 2 + 0] = a0 + b[0];
        out[gwarp * 2 + 1] = a1 + b[1];
    }
}

// ---------------- launch ----------------
extern "C" void kernel_launch(void* const* d_in, const int* in_sizes, int n_in,
                              void* d_out, int out_size) {
    (void)in_sizes; (void)n_in; (void)out_size;
    const float* x   = (const float*)d_in[0];
    const float* x1  = (const float*)d_in[1];
    const int*   ei  = (const int*)d_in[2];
    const int*   src = ei;
    const int*   dst = ei + EE;
    const float* gw0 = (const float*)d_in[3];
    const float* gb0 = (const float*)d_in[4];
    const float* gw1 = (const float*)d_in[5];
    const float* gb1 = (const float*)d_in[6];
    const float* wl0 = (const float*)d_in[7];
    const float* bl0 = (const float*)d_in[8];
    const float* wr0 = (const float*)d_in[9];
    const float* wl1 = (const float*)d_in[10];
    const float* bl1 = (const float*)d_in[11];
    const float* wr1 = (const float*)d_in[12];
    const float* lw  = (const float*)d_in[13];
    const float* lb  = (const float*)d_in[14];
    float* out = (float*)d_out;

    float *p_h1, *p_s, *p_h1b, *p_hcat, *p_m0, *p_h2, *p_m1, *p_h3;
    cudaGetSymbolAddress((void**)&p_h1, d_h1);
    cudaGetSymbolAddress((void**)&p_s, d_s);
    cudaGetSymbolAddress((void**)&p_h1b, d_h1b);
    cudaGetSymbolAddress((void**)&p_hcat, d_hcat);
    cudaGetSymbolAddress((void**)&p_m0, d_m0);
    cudaGetSymbolAddress((void**)&p_h2, d_h2);
    cudaGetSymbolAddress((void**)&p_m1, d_m1);
    cudaGetSymbolAddress((void**)&p_h3, d_h3);

    // CSR build + degrees
    k_zero_cnt<<<(NN + 255) / 256, 256>>>();
    k_count<<<(EE + 255) / 256, 256>>>(dst);
    k_scan1<<<NB_SCAN, 1024>>>();
    k_scan2<<<1, 32>>>();
    k_scan3<<<(NN + 1 + 255) / 256, 256>>>();
    k_fill<<<(EE + 255) / 256, 256>>>(src, dst);

    // GIN layer 0 (K = 1)
    k_gin0_agg<<<(NN + 255) / 256, 256>>>(x1);
    k_gin0_act<<<(NN * HH + 255) / 256, 256>>>(gw0, gb0);

    dim3 gemm_grid(HH / 64, (NN + 127) / 128);

    // GIN layer 1
    k_agg<<<NN, 64>>>(p_h1, p_s, HH / 4, 0);
    k_gemm<<<gemm_grid, 256>>>(p_s, gw1, HH, nullptr, nullptr, 0, gb1, p_h1b, 1);

    // concat + SAGE layer 0
    k_concat<<<(NN * FH + 255) / 256, 256>>>(x);
    k_agg<<<NN, 64>>>(p_hcat, p_m0, FH / 4, 1);
    k_gemm<<<gemm_grid, 256>>>(p_m0, wl0, FH, p_hcat, wr0, FH, bl0, p_h2, 2);

    // SAGE layer 1
    k_agg<<<NN, 64>>>(p_h2, p_m1, HH / 4, 1);
    k_gemm<<<gemm_grid, 256>>>(p_m1, wl1, HH, p_h2, wr1, HH, bl1, p_h3, 2);

    // output head
    k_out<<<(NN * 32 + 127) / 128, 128>>>(p_h3, lw, lb, out);
}

// round 2
// speedup vs baseline: 1.2453x; 1.2453x over previous
#include <cuda_runtime.h>
#include <cuda_bf16.h>
#include <math.h>
#include <stdint.h>

// Problem constants
static const int NN = 50000;
static const int FF = 64;
static const int HH = 256;
static const int EE = 1600000;
static const int FH = 320;                     // FF + HH
static const int NB_SCAN = (NN + 1023) / 1024; // 49

typedef __nv_bfloat16 bf16;
typedef __nv_bfloat162 bf162;

// ---------------- scratch (__device__ globals; allocation-free) ----------------
__device__ int   d_cnt[NN];
__device__ int   d_rowptr[NN + 1];
__device__ int   d_fill[NN];
__device__ int   d_col[EE];
__device__ int   d_bsum[64];
__device__ float d_deg[NN];
__device__ float d_g1[NN];
// fp32 feature buffers (aggregation inputs / final head input)
__device__ __align__(16) float d_h1 [NN * HH];  // tanh(gin0)
__device__ __align__(16) float d_h1b[NN * HH];  // tanh(gin1)
__device__ __align__(16) float d_hcat[NN * FH]; // [x | h1b]
__device__ __align__(16) float d_h2 [NN * HH];  // relu(sage0)
__device__ __align__(16) float d_h3 [NN * HH];  // relu(sage1)
// bf16 hi/lo split panels (GEMM A operands)
__device__ __align__(16) bf16 d_sh [NN * HH];
__device__ __align__(16) bf16 d_sl [NN * HH];
__device__ __align__(16) bf16 d_hch[NN * FH];
__device__ __align__(16) bf16 d_hcl[NN * FH];
__device__ __align__(16) bf16 d_m0h[NN * FH];
__device__ __align__(16) bf16 d_m0l[NN * FH];
__device__ __align__(16) bf16 d_h2h[NN * HH];
__device__ __align__(16) bf16 d_h2l[NN * HH];
__device__ __align__(16) bf16 d_m1h[NN * HH];
__device__ __align__(16) bf16 d_m1l[NN * HH];
// bf16 hi/lo weights
__device__ __align__(16) bf16 d_gw1h[HH * HH];
__device__ __align__(16) bf16 d_gw1l[HH * HH];
__device__ __align__(16) bf16 d_wl0h[FH * HH];
__device__ __align__(16) bf16 d_wl0l[FH * HH];
__device__ __align__(16) bf16 d_wr0h[FH * HH];
__device__ __align__(16) bf16 d_wr0l[FH * HH];
__device__ __align__(16) bf16 d_wl1h[HH * HH];
__device__ __align__(16) bf16 d_wl1l[HH * HH];
__device__ __align__(16) bf16 d_wr1h[HH * HH];
__device__ __align__(16) bf16 d_wr1l[HH * HH];

// ---------------- CSR build ----------------
__global__ void k_zero_cnt() {
    int i = blockIdx.x * blockDim.x + threadIdx.x;
    if (i < NN) d_cnt[i] = 0;
}

__global__ void k_count(const int* __restrict__ dst) {
    int e = blockIdx.x * blockDim.x + threadIdx.x;
    if (e < EE) atomicAdd(&d_cnt[dst[e]], 1);
}

__global__ void k_scan1() {
    __shared__ int sh[1024];
    int tid = threadIdx.x;
    int i = blockIdx.x * 1024 + tid;
    int v = (i < NN) ? d_cnt[i] : 0;
    sh[tid] = v;
    __syncthreads();
#pragma unroll
    for (int off = 1; off < 1024; off <<= 1) {
        int t = (tid >= off) ? sh[tid - off] : 0;
        __syncthreads();
        sh[tid] += t;
        __syncthreads();
    }
    if (i < NN) d_rowptr[i] = sh[tid] - v; // exclusive
    if (tid == 1023) d_bsum[blockIdx.x] = sh[1023];
}

__global__ void k_scan2() {
    if (threadIdx.x == 0 && blockIdx.x == 0) {
        int run = 0;
        for (int b = 0; b < NB_SCAN; b++) {
            int t = d_bsum[b];
            d_bsum[b] = run;
            run += t;
        }
    }
}

__global__ void k_scan3() {
    int i = blockIdx.x * blockDim.x + threadIdx.x;
    if (i < NN) {
        int r = d_rowptr[i] + d_bsum[i >> 10];
        d_rowptr[i] = r;
        d_fill[i] = r;
        float c = (float)d_cnt[i];
        d_deg[i] = fmaxf(c, 1.0f);
    } else if (i == NN) {
        d_rowptr[NN] = EE;
    }
}

__global__ void k_fill(const int* __restrict__ src, const int* __restrict__ dst) {
    int e = blockIdx.x * blockDim.x + threadIdx.x;
    if (e < EE) {
        int pos = atomicAdd(&d_fill[dst[e]], 1);
        d_col[pos] = src[e];
    }
}

// ---------------- GIN0 (K = 1) ----------------
__global__ void k_gin0_agg(const float* __restrict__ x1) {
    int i = blockIdx.x * blockDim.x + threadIdx.x;
    if (i >= NN) return;
    int beg = d_rowptr[i], end = d_rowptr[i + 1];
    float s = x1[i]; // self (eps = 0)
    for (int j = beg; j < end; j++) s += x1[d_col[j]];
    d_g1[i] = s;
}

__global__ void k_gin0_act(const float* __restrict__ w0, const float* __restrict__ b0) {
    int idx = blockIdx.x * blockDim.x + threadIdx.x;
    if (idx >= NN * HH) return;
    int i = idx >> 8;       // / 256
    int c = idx & 255;      // % 256
    d_h1[idx] = tanhf(d_g1[i] * w0[c] + b0[c]);
}

// ---------------- split helpers ----------------
__device__ __forceinline__ void split2(float v, bf16& h, bf16& l) {
    h = __float2bfloat16(v);
    l = __float2bfloat16(v - __bfloat162float(h));
}

__global__ void k_split_w(const float* __restrict__ W, bf16* __restrict__ Wh,
                          bf16* __restrict__ Wl, int n) {
    int i = blockIdx.x * blockDim.x + threadIdx.x;
    if (i < n) {
        bf16 h, l;
        split2(W[i], h, l);
        Wh[i] = h; Wl[i] = l;
    }
}

// ---------------- aggregation: fp32 in -> bf16 hi/lo out ----------------
// mode 0 = self+sum (GIN), 1 = mean (SAGE)
__global__ void k_agg(const float* __restrict__ in, bf16* __restrict__ oh,
                      bf16* __restrict__ ol, int D4, int mode) {
    int node = blockIdx.x;
    int t = threadIdx.x; // 64 threads
    int beg = d_rowptr[node], end = d_rowptr[node + 1];
    const float4* in4 = (const float4*)in;
    bool has1 = (t + 64) < D4; // D4 = 64 (H) or 80 (FH)
    float4 a0 = make_float4(0.f, 0.f, 0.f, 0.f);
    float4 a1 = make_float4(0.f, 0.f, 0.f, 0.f);
    int snext = (beg < end) ? d_col[beg] : 0;
    for (int j = beg; j < end; j++) {
        int s = snext;
        if (j + 1 < end) snext = d_col[j + 1];
        const float4* r = in4 + (long)s * D4;
        float4 v = r[t];
        a0.x += v.x; a0.y += v.y; a0.z += v.z; a0.w += v.w;
        if (has1) {
            float4 w = r[t + 64];
            a1.x += w.x; a1.y += w.y; a1.z += w.z; a1.w += w.w;
        }
    }
    const float4* me = in4 + (long)node * D4;
    if (mode == 0) { // self + sum
        float4 v = me[t];
        a0.x += v.x; a0.y += v.y; a0.z += v.z; a0.w += v.w;
        if (has1) {
            float4 w = me[t + 64];
            a1.x += w.x; a1.y += w.y; a1.z += w.z; a1.w += w.w;
        }
    } else { // mean
        float inv = 1.0f / d_deg[node];
        a0.x *= inv; a0.y *= inv; a0.z *= inv; a0.w *= inv;
        a1.x *= inv; a1.y *= inv; a1.z *= inv; a1.w *= inv;
    }
    long base = (long)node * D4 * 4 + t * 4;
    bf16 h, l;
    split2(a0.x, h, l); oh[base + 0] = h; ol[base + 0] = l;
    split2(a0.y, h, l); oh[base + 1] = h; ol[base + 1] = l;
    split2(a0.z, h, l); oh[base + 2] = h; ol[base + 2] = l;
    split2(a0.w, h, l); oh[base + 3] = h; ol[base + 3] = l;
    if (has1) {
        long b2 = base + 256;
        split2(a1.x, h, l); oh[b2 + 0] = h; ol[b2 + 0] = l;
        split2(a1.y, h, l); oh[b2 + 1] = h; ol[b2 + 1] = l;
        split2(a1.z, h, l); oh[b2 + 2] = h; ol[b2 + 2] = l;
        split2(a1.w, h, l); oh[b2 + 3] = h; ol[b2 + 3] = l;
    }
}

// ---------------- concat [x | h1b] -> fp32 + bf16 hi/lo ----------------
__global__ void k_concat(const float* __restrict__ x) {
    int idx = blockIdx.x * blockDim.x + threadIdx.x;
    if (idx >= NN * FH) return;
    int i = idx / FH;
    int c = idx - i * FH;
    float v = (c < FF) ? x[i * FF + c] : d_h1b[i * HH + (c - FF)];
    d_hcat[idx] = v;
    bf16 h, l;
    split2(v, h, l);
    d_hch[idx] = h;
    d_hcl[idx] = l;
}

// ---------------- bf16 tensor-core multi-panel GEMM ----------------
// C[M, 256] = act( sum_p A_p[M,K] @ B_p[K,256] + bias )
// act: 1 tanh, 2 relu
struct PanelArgs {
    const bf16* A[6];
    const bf16* B[6];
};

__global__ void __launch_bounds__(256, 2)
k_mma(PanelArgs args, int nP, int K,
      const float* __restrict__ bias,
      float* __restrict__ Cf,
      bf16* __restrict__ Ch, bf16* __restrict__ Cl,
      int act, int M)
{
    const int BM = 128, BN = 64, BK = 32;
    // padded rows to stagger 16B bank chunks for ldmatrix
    __shared__ bf16 As[128 * 40]; // row pitch 40 bf16 = 80B
    __shared__ bf16 Bs[32 * 72];  // row pitch 72 bf16 = 144B

    int tid = threadIdx.x;
    int lane = tid & 31, warp = tid >> 5;
    int wm = warp & 3, wn = warp >> 2;       // 4 x 2 warp grid
    int blockRow = blockIdx.y * BM;
    int blockCol = blockIdx.x * BN;

    int perP = K / BK;
    int nIter = nP * perP;

    int aRow = tid >> 2;   // 0..63
    int aChunk = tid & 3;  // *8 bf16
    int bRow = tid >> 3;   // 0..31
    int bChunk = tid & 7;  // *8 bf16

    uint4 ra0, ra1, rb;
    auto load_tile = [&](int it) {
        int p = it / perP;
        int kk = (it - p * perP) * BK;
        const bf16* A = args.A[p];
        const bf16* B = args.B[p];
        int r0 = blockRow + aRow;
        int r1 = r0 + 64;
        ra0 = make_uint4(0, 0, 0, 0);
        ra1 = make_uint4(0, 0, 0, 0);
        if (r0 < M) ra0 = *(const uint4*)(A + (size_t)r0 * K + kk + aChunk * 8);
        if (r1 < M) ra1 = *(const uint4*)(A + (size_t)r1 * K + kk + aChunk * 8);
        rb = *(const uint4*)(B + (size_t)(kk + bRow) * 256 + blockCol + bChunk * 8);
    };

    float c[2][4][4];
#pragma unroll
    for (int mt = 0; mt < 2; mt++)
#pragma unroll
        for (int nt = 0; nt < 4; nt++)
#pragma unroll
            for (int q = 0; q < 4; q++) c[mt][nt][q] = 0.f;

    load_tile(0);
#pragma unroll 1
    for (int it = 0; it < nIter; it++) {
        *(uint4*)&As[aRow * 40 + aChunk * 8] = ra0;
        *(uint4*)&As[(aRow + 64) * 40 + aChunk * 8] = ra1;
        *(uint4*)&Bs[bRow * 72 + bChunk * 8] = rb;
        __syncthreads();
        if (it + 1 < nIter) load_tile(it + 1);

#pragma unroll
        for (int ks = 0; ks < 2; ks++) {
            uint32_t af[2][4], bfr[2][4];
#pragma unroll
            for (int mt = 0; mt < 2; mt++) {
                int row = wm * 32 + mt * 16 + (lane & 15);
                int col = ks * 16 + (lane >> 4) * 8;
                uint32_t addr = (uint32_t)__cvta_generic_to_shared(&As[row * 40 + col]);
                asm volatile(
                    "ldmatrix.sync.aligned.m8n8.x4.shared.b16 {%0,%1,%2,%3}, [%4];"
                    : "=r"(af[mt][0]), "=r"(af[mt][1]), "=r"(af[mt][2]), "=r"(af[mt][3])
                    : "r"(addr));
            }
#pragma unroll
            for (int bt = 0; bt < 2; bt++) {
                int row = ks * 16 + (lane & 15);
                int col = wn * 32 + bt * 16 + (lane >> 4) * 8;
                uint32_t addr = (uint32_t)__cvta_generic_to_shared(&Bs[row * 72 + col]);
                asm volatile(
                    "ldmatrix.sync.aligned.m8n8.x4.trans.shared.b16 {%0,%1,%2,%3}, [%4];"
                    : "=r"(bfr[bt][0]), "=r"(bfr[bt][1]), "=r"(bfr[bt][2]), "=r"(bfr[bt][3])
                    : "r"(addr));
            }
#pragma unroll
            for (int mt = 0; mt < 2; mt++)
#pragma unroll
                for (int nt = 0; nt < 4; nt++) {
                    const uint32_t b0 = bfr[nt >> 1][(nt & 1) * 2];
                    const uint32_t b1 = bfr[nt >> 1][(nt & 1) * 2 + 1];
                    asm volatile(
                        "mma.sync.aligned.m16n8k16.row.col.f32.bf16.bf16.f32 "
                        "{%0,%1,%2,%3}, {%4,%5,%6,%7}, {%8,%9}, {%0,%1,%2,%3};"
                        : "+f"(c[mt][nt][0]), "+f"(c[mt][nt][1]),
                          "+f"(c[mt][nt][2]), "+f"(c[mt][nt][3])
                        : "r"(af[mt][0]), "r"(af[mt][1]), "r"(af[mt][2]), "r"(af[mt][3]),
                          "r"(b0), "r"(b1));
                }
        }
        __syncthreads();
    }

    // epilogue
#pragma unroll
    for (int mt = 0; mt < 2; mt++) {
#pragma unroll
        for (int half = 0; half < 2; half++) {
            int row = blockRow + wm * 32 + mt * 16 + half * 8 + (lane >> 2);
            if (row >= M) continue;
#pragma unroll
            for (int nt = 0; nt < 4; nt++) {
                int col = blockCol + wn * 32 + nt * 8 + (lane & 3) * 2;
                float v0 = c[mt][nt][half * 2 + 0] + bias[col];
                float v1 = c[mt][nt][half * 2 + 1] + bias[col + 1];
                if (act == 1) { v0 = tanhf(v0); v1 = tanhf(v1); }
                else if (act == 2) { v0 = fmaxf(v0, 0.f); v1 = fmaxf(v1, 0.f); }
                size_t off = (size_t)row * 256 + col;
                float2 f2; f2.x = v0; f2.y = v1;
                *(float2*)&Cf[off] = f2;
                if (Ch) {
                    bf16 h0, l0, h1, l1;
                    split2(v0, h0, l0);
                    split2(v1, h1, l1);
                    bf162 ph; ph.x = h0; ph.y = h1;
                    bf162 pl; pl.x = l0; pl.y = l1;
                    *(bf162*)&Ch[off] = ph;
                    *(bf162*)&Cl[off] = pl;
                }
            }
        }
    }
}

// ---------------- final linear [N,256] @ [256,2] + b ----------------
__global__ void k_out(const float* __restrict__ h, const float* __restrict__ W,
                      const float* __restrict__ b, float* __restrict__ out) {
    int gwarp = (blockIdx.x * blockDim.x + threadIdx.x) >> 5;
    int lane = threadIdx.x & 31;
    if (gwarp >= NN) return;
    const float* row = h + (long)gwarp * HH;
    float a0 = 0.f, a1 = 0.f;
#pragma unroll
    for (int k = lane; k < HH; k += 32) {
        float v = row[k];
        a0 += v * W[k * 2 + 0];
        a1 += v * W[k * 2 + 1];
    }
#pragma unroll
    for (int o = 16; o > 0; o >>= 1) {
        a0 += __shfl_down_sync(0xFFFFFFFFu, a0, o);
        a1 += __shfl_down_sync(0xFFFFFFFFu, a1, o);
    }
    if (lane == 0) {
        out[gwarp * 2 + 0] = a0 + b[0];
        out[gwarp * 2 + 1] = a1 + b[1];
    }
}

// ---------------- launch ----------------
extern "C" void kernel_launch(void* const* d_in, const int* in_sizes, int n_in,
                              void* d_out, int out_size) {
    (void)in_sizes; (void)n_in; (void)out_size;
    const float* x   = (const float*)d_in[0];
    const float* x1  = (const float*)d_in[1];
    const int*   ei  = (const int*)d_in[2];
    const int*   src = ei;
    const int*   dst = ei + EE;
    const float* gw0 = (const float*)d_in[3];
    const float* gb0 = (const float*)d_in[4];
    const float* gw1 = (const float*)d_in[5];
    const float* gb1 = (const float*)d_in[6];
    const float* wl0 = (const float*)d_in[7];
    const float* bl0 = (const float*)d_in[8];
    const float* wr0 = (const float*)d_in[9];
    const float* wl1 = (const float*)d_in[10];
    const float* bl1 = (const float*)d_in[11];
    const float* wr1 = (const float*)d_in[12];
    const float* lw  = (const float*)d_in[13];
    const float* lb  = (const float*)d_in[14];
    float* out = (float*)d_out;

    float *p_h1b, *p_h2, *p_h3;
    cudaGetSymbolAddress((void**)&p_h1b, d_h1b);
    cudaGetSymbolAddress((void**)&p_h2, d_h2);
    cudaGetSymbolAddress((void**)&p_h3, d_h3);
    float *p_h1, *p_hcat;
    cudaGetSymbolAddress((void**)&p_h1, d_h1);
    cudaGetSymbolAddress((void**)&p_hcat, d_hcat);

    bf16 *p_sh, *p_sl, *p_hch, *p_hcl, *p_m0h, *p_m0l, *p_h2h, *p_h2l, *p_m1h, *p_m1l;
    cudaGetSymbolAddress((void**)&p_sh, d_sh);
    cudaGetSymbolAddress((void**)&p_sl, d_sl);
    cudaGetSymbolAddress((void**)&p_hch, d_hch);
    cudaGetSymbolAddress((void**)&p_hcl, d_hcl);
    cudaGetSymbolAddress((void**)&p_m0h, d_m0h);
    cudaGetSymbolAddress((void**)&p_m0l, d_m0l);
    cudaGetSymbolAddress((void**)&p_h2h, d_h2h);
    cudaGetSymbolAddress((void**)&p_h2l, d_h2l);
    cudaGetSymbolAddress((void**)&p_m1h, d_m1h);
    cudaGetSymbolAddress((void**)&p_m1l, d_m1l);

    bf16 *p_gw1h, *p_gw1l, *p_wl0h, *p_wl0l, *p_wr0h, *p_wr0l,
         *p_wl1h, *p_wl1l, *p_wr1h, *p_wr1l;
    cudaGetSymbolAddress((void**)&p_gw1h, d_gw1h);
    cudaGetSymbolAddress((void**)&p_gw1l, d_gw1l);
    cudaGetSymbolAddress((void**)&p_wl0h, d_wl0h);
    cudaGetSymbolAddress((void**)&p_wl0l, d_wl0l);
    cudaGetSymbolAddress((void**)&p_wr0h, d_wr0h);
    cudaGetSymbolAddress((void**)&p_wr0l, d_wr0l);
    cudaGetSymbolAddress((void**)&p_wl1h, d_wl1h);
    cudaGetSymbolAddress((void**)&p_wl1l, d_wl1l);
    cudaGetSymbolAddress((void**)&p_wr1h, d_wr1h);
    cudaGetSymbolAddress((void**)&p_wr1l, d_wr1l);

    // CSR build + degrees
    k_zero_cnt<<<(NN + 255) / 256, 256>>>();
    k_count<<<(EE + 255) / 256, 256>>>(dst);
    k_scan1<<<NB_SCAN, 1024>>>();
    k_scan2<<<1, 32>>>();
    k_scan3<<<(NN + 1 + 255) / 256, 256>>>();
    k_fill<<<(EE + 255) / 256, 256>>>(src, dst);

    // weight splits
    k_split_w<<<(HH * HH + 255) / 256, 256>>>(gw1, p_gw1h, p_gw1l, HH * HH);
    k_split_w<<<(FH * HH + 255) / 256, 256>>>(wl0, p_wl0h, p_wl0l, FH * HH);
    k_split_w<<<(FH * HH + 255) / 256, 256>>>(wr0, p_wr0h, p_wr0l, FH * HH);
    k_split_w<<<(HH * HH + 255) / 256, 256>>>(wl1, p_wl1h, p_wl1l, HH * HH);
    k_split_w<<<(HH * HH + 255) / 256, 256>>>(wr1, p_wr1h, p_wr1l, HH * HH);

    // GIN layer 0 (K = 1)
    k_gin0_agg<<<(NN + 255) / 256, 256>>>(x1);
    k_gin0_act<<<(NN * HH + 255) / 256, 256>>>(gw0, gb0);

    dim3 gemm_grid(HH / 64, (NN + 127) / 128);

    // GIN layer 1: s = h1 + agg(h1); h1b = tanh(s @ gw1 + gb1)
    k_agg<<<NN, 64>>>(p_h1, p_sh, p_sl, HH / 4, 0);
    {
        PanelArgs pa;
        pa.A[0] = p_sh;  pa.B[0] = p_gw1h;
        pa.A[1] = p_sl;  pa.B[1] = p_gw1h;
        pa.A[2] = p_sh;  pa.B[2] = p_gw1l;
        for (int i = 3; i < 6; i++) { pa.A[i] = nullptr; pa.B[i] = nullptr; }
        k_mma<<<gemm_grid, 256>>>(pa, 3, HH, gb1, p_h1b, nullptr, nullptr, 1, NN);
    }

    // concat + SAGE layer 0
    k_concat<<<(NN * FH + 255) / 256, 256>>>(x);
    k_agg<<<NN, 64>>>(p_hcat, p_m0h, p_m0l, FH / 4, 1);
    {
        PanelArgs pa;
        pa.A[0] = p_m0h; pa.B[0] = p_wl0h;
        pa.A[1] = p_m0l; pa.B[1] = p_wl0h;
        pa.A[2] = p_m0h; pa.B[2] = p_wl0l;
        pa.A[3] = p_hch; pa.B[3] = p_wr0h;
        pa.A[4] = p_hcl; pa.B[4] = p_wr0h;
        pa.A[5] = p_hch; pa.B[5] = p_wr0l;
        k_mma<<<gemm_grid, 256>>>(pa, 6, FH, bl0, p_h2, p_h2h, p_h2l, 2, NN);
    }

    // SAGE layer 1
    k_agg<<<NN, 64>>>(p_h2, p_m1h, p_m1l, HH / 4, 1);
    {
        PanelArgs pa;
        pa.A[0] = p_m1h; pa.B[0] = p_wl1h;
        pa.A[1] = p_m1l; pa.B[1] = p_wl1h;
        pa.A[2] = p_m1h; pa.B[2] = p_wl1l;
        pa.A[3] = p_h2h; pa.B[3] = p_wr1h;
        pa.A[4] = p_h2l; pa.B[4] = p_wr1h;
        pa.A[5] = p_h2h; pa.B[5] = p_wr1l;
        k_mma<<<gemm_grid, 256>>>(pa, 6, HH, bl1, p_h3, nullptr, nullptr, 2, NN);
    }

    // output head
    k_out<<<(NN * 32 + 127) / 128, 128>>>(p_h3, lw, lb, out);
}

// round 4
// speedup vs baseline: 1.4771x; 1.1862x over previous
#include <cuda_runtime.h>
#include <cuda_bf16.h>
#include <math.h>
#include <stdint.h>

// Problem constants
static const int NN = 50000;
static const int FF = 64;
static const int HH = 256;
static const int EE = 1600000;
static const int FH = 320;                     // FF + HH
static const int NB_SCAN = (NN + 1023) / 1024; // 49
static const int MBLK = (NN + 127) / 128;      // 391

typedef __nv_bfloat16 bf16;
typedef __nv_bfloat162 bf162;

// ---------------- scratch (__device__ globals; allocation-free) ----------------
__device__ int   d_cnt[NN];
__device__ int   d_rowptr[NN + 1];
__device__ int   d_fill[NN];
__device__ int   d_col[EE];
__device__ int   d_bsum[64];
__device__ float d_deg[NN];
__device__ float d_g1[NN];
// bf16 hi/lo GEMM A operands
__device__ __align__(16) bf16 d_h1h[NN * HH];   // tanh(gin0) hi
__device__ __align__(16) bf16 d_h1l[NN * HH];   // tanh(gin0) lo
__device__ __align__(16) bf16 d_hch[NN * FH];   // [x | h1b] hi
__device__ __align__(16) bf16 d_hcl[NN * FH];   // [x | h1b] lo
__device__ __align__(16) bf16 d_h2h[NN * HH];   // relu(sage0) hi
__device__ __align__(16) bf16 d_h2l[NN * HH];   // relu(sage0) lo
// fp32 projection outputs
__device__ __align__(16) float d_P1[NN * HH];        // h1 @ gw1      [N,256]
__device__ __align__(16) float d_P2[NN * 2 * HH];    // A @ [Wl|Wr]   [N,512]
// bf16 hi/lo weights
__device__ __align__(16) bf16 d_gw1h[HH * HH];       // [256,256]
__device__ __align__(16) bf16 d_gw1l[HH * HH];
__device__ __align__(16) bf16 d_w0h[FH * 2 * HH];    // [320,512] = [Wl0|Wr0]
__device__ __align__(16) bf16 d_w0l[FH * 2 * HH];
__device__ __align__(16) bf16 d_w1h[HH * 2 * HH];    // [256,512] = [Wl1|Wr1]
__device__ __align__(16) bf16 d_w1l[HH * 2 * HH];

// ---------------- CSR build ----------------
__global__ void k_zero_cnt() {
    int i = blockIdx.x * blockDim.x + threadIdx.x;
    if (i < NN) d_cnt[i] = 0;
}

__global__ void k_count(const int* __restrict__ dst) {
    int e = blockIdx.x * blockDim.x + threadIdx.x;
    if (e < EE) atomicAdd(&d_cnt[dst[e]], 1);
}

__global__ void k_scan1() {
    __shared__ int sh[1024];
    int tid = threadIdx.x;
    int i = blockIdx.x * 1024 + tid;
    int v = (i < NN) ? d_cnt[i] : 0;
    sh[tid] = v;
    __syncthreads();
#pragma unroll
    for (int off = 1; off < 1024; off <<= 1) {
        int t = (tid >= off) ? sh[tid - off] : 0;
        __syncthreads();
        sh[tid] += t;
        __syncthreads();
    }
    if (i < NN) d_rowptr[i] = sh[tid] - v; // exclusive
    if (tid == 1023) d_bsum[blockIdx.x] = sh[1023];
}

__global__ void k_scan2() {
    if (threadIdx.x == 0 && blockIdx.x == 0) {
        int run = 0;
        for (int b = 0; b < NB_SCAN; b++) {
            int t = d_bsum[b];
            d_bsum[b] = run;
            run += t;
        }
    }
}

__global__ void k_scan3() {
    int i = blockIdx.x * blockDim.x + threadIdx.x;
    if (i < NN) {
        int r = d_rowptr[i] + d_bsum[i >> 10];
        d_rowptr[i] = r;
        d_fill[i] = r;
        float c = (float)d_cnt[i];
        d_deg[i] = fmaxf(c, 1.0f);
    } else if (i == NN) {
        d_rowptr[NN] = EE;
    }
}

__global__ void k_fill(const int* __restrict__ src, const int* __restrict__ dst) {
    int e = blockIdx.x * blockDim.x + threadIdx.x;
    if (e < EE) {
        int pos = atomicAdd(&d_fill[dst[e]], 1);
        d_col[pos] = src[e];
    }
}

// ---------------- split helpers ----------------
__device__ __forceinline__ void split2(float v, bf16& h, bf16& l) {
    h = __float2bfloat16(v);
    l = __float2bfloat16(v - __bfloat162float(h));
}

// W [K, 256] row-major -> Wh/Wl [K, pitch] with column offset (for [Wl|Wr] packing)
__global__ void k_split_w(const float* __restrict__ W, bf16* __restrict__ Wh,
                          bf16* __restrict__ Wl, int n, int pitch, int coloff) {
    int i = blockIdx.x * blockDim.x + threadIdx.x;
    if (i >= n) return;
    int k = i >> 8;
    int c = i & 255;
    bf16 h, l;
    split2(W[i], h, l);
    size_t o = (size_t)k * pitch + coloff + c;
    Wh[o] = h; Wl[o] = l;
}

// x [N,64] -> hch/hcl columns 0..63 (pitch 320)
__global__ void k_split_x(const float* __restrict__ x) {
    int i = blockIdx.x * blockDim.x + threadIdx.x;
    if (i >= NN * FF) return;
    int r = i >> 6;
    int c = i & 63;
    bf16 h, l;
    split2(x[i], h, l);
    size_t o = (size_t)r * FH + c;
    d_hch[o] = h; d_hcl[o] = l;
}

// ---------------- GIN0 (K = 1) ----------------
__global__ void k_gin0_agg(const float* __restrict__ x1) {
    int i = blockIdx.x * blockDim.x + threadIdx.x;
    if (i >= NN) return;
    int beg = d_rowptr[i], end = d_rowptr[i + 1];
    float s = x1[i]; // self (eps = 0)
    for (int j = beg; j < end; j++) s += x1[d_col[j]];
    d_g1[i] = s;
}

__global__ void k_gin0_act(const float* __restrict__ w0, const float* __restrict__ b0) {
    int idx = blockIdx.x * blockDim.x + threadIdx.x;
    if (idx >= NN * HH) return;
    int i = idx >> 8;
    int c = idx & 255;
    float v = tanhf(d_g1[i] * w0[c] + b0[c]);
    bf16 h, l;
    split2(v, h, l);
    d_h1h[idx] = h;
    d_h1l[idx] = l;
}

// ---------------- fused gather + combine kernels ----------------
// Each: 1 block (64 threads) per node; thread t handles float4 cols [4t, 4t+4).

// GIN1: out = tanh(P1[node] + sum_nbr P1[nbr] + b); write hi/lo into hcat cols 64..319
__global__ void k_comb_gin(const float* __restrict__ P,
                           const float* __restrict__ bias) {
    int node = blockIdx.x;
    int t = threadIdx.x;
    int beg = d_rowptr[node], end = d_rowptr[node + 1];
    const float4* P4 = (const float4*)P;
    float4 a = P4[(size_t)node * 64 + t]; // self
    int snext = (beg < end) ? d_col[beg] : 0;
    for (int j = beg; j < end; j++) {
        int s = snext;
        if (j + 1 < end) snext = d_col[j + 1];
        float4 v = P4[(size_t)s * 64 + t];
        a.x += v.x; a.y += v.y; a.z += v.z; a.w += v.w;
    }
    float4 bv = *(const float4*)&bias[t * 4];
    a.x = tanhf(a.x + bv.x); a.y = tanhf(a.y + bv.y);
    a.z = tanhf(a.z + bv.z); a.w = tanhf(a.w + bv.w);
    size_t o = (size_t)node * FH + 64 + t * 4;
    bf16 h0, l0, h1, l1;
    split2(a.x, h0, l0); split2(a.y, h1, l1);
    bf162 ph, pl;
    ph.x = h0; ph.y = h1; pl.x = l0; pl.y = l1;
    *(bf162*)&d_hch[o] = ph; *(bf162*)&d_hcl[o] = pl;
    split2(a.z, h0, l0); split2(a.w, h1, l1);
    ph.x = h0; ph.y = h1; pl.x = l0; pl.y = l1;
    *(bf162*)&d_hch[o + 2] = ph; *(bf162*)&d_hcl[o + 2] = pl;
}

// SAGE: out = relu(sum_nbr P[nbr][0:256]/deg + b + P[node][256:512]); write h2 hi/lo
__global__ void k_comb_sage(const float* __restrict__ P,
                            const float* __restrict__ bias,
                            bf16* __restrict__ oh, bf16* __restrict__ ol) {
    int node = blockIdx.x;
    int t = threadIdx.x;
    int beg = d_rowptr[node], end = d_rowptr[node + 1];
    const float4* P4 = (const float4*)P; // pitch 128 float4
    float4 a = make_float4(0.f, 0.f, 0.f, 0.f);
    int snext = (beg < end) ? d_col[beg] : 0;
    for (int j = beg; j < end; j++) {
        int s = snext;
        if (j + 1 < end) snext = d_col[j + 1];
        float4 v = P4[(size_t)s * 128 + t];
        a.x += v.x; a.y += v.y; a.z += v.z; a.w += v.w;
    }
    float inv = 1.0f / d_deg[node];
    float4 r = P4[(size_t)node * 128 + 64 + t]; // self @ Wr (cols 256..511)
    float4 bv = *(const float4*)&bias[t * 4];
    a.x = fmaxf(a.x * inv + bv.x + r.x, 0.f);
    a.y = fmaxf(a.y * inv + bv.y + r.y, 0.f);
    a.z = fmaxf(a.z * inv + bv.z + r.z, 0.f);
    a.w = fmaxf(a.w * inv + bv.w + r.w, 0.f);
    size_t o = (size_t)node * HH + t * 4;
    bf16 h0, l0, h1, l1;
    split2(a.x, h0, l0); split2(a.y, h1, l1);
    bf162 ph, pl;
    ph.x = h0; ph.y = h1; pl.x = l0; pl.y = l1;
    *(bf162*)&oh[o] = ph; *(bf162*)&ol[o] = pl;
    split2(a.z, h0, l0); split2(a.w, h1, l1);
    ph.x = h0; ph.y = h1; pl.x = l0; pl.y = l1;
    *(bf162*)&oh[o + 2] = ph; *(bf162*)&ol[o + 2] = pl;
}

// SAGE final: same combine, then fused output head: out[node] = v . lw + lb  (256 -> 2)
__global__ void k_comb_sage_out(const float* __restrict__ P,
                                const float* __restrict__ bias,
                                const float* __restrict__ lw,
                                const float* __restrict__ lb,
                                float* __restrict__ out) {
    int node = blockIdx.x;
    int t = threadIdx.x;
    int lane = t & 31, warp = t >> 5;
    int beg = d_rowptr[node], end = d_rowptr[node + 1];
    const float4* P4 = (const float4*)P;
    float4 a = make_float4(0.f, 0.f, 0.f, 0.f);
    int snext = (beg < end) ? d_col[beg] : 0;
    for (int j = beg; j < end; j++) {
        int s = snext;
        if (j + 1 < end) snext = d_col[j + 1];
        float4 v = P4[(size_t)s * 128 + t];
        a.x += v.x; a.y += v.y; a.z += v.z; a.w += v.w;
    }
    float inv = 1.0f / d_deg[node];
    float4 r = P4[(size_t)node * 128 + 64 + t];
    float4 bv = *(const float4*)&bias[t * 4];
    a.x = fmaxf(a.x * inv + bv.x + r.x, 0.f);
    a.y = fmaxf(a.y * inv + bv.y + r.y, 0.f);
    a.z = fmaxf(a.z * inv + bv.z + r.z, 0.f);
    a.w = fmaxf(a.w * inv + bv.w + r.w, 0.f);
    // head dot: cols c = 4t..4t+3
    int c = t * 4;
    float p0 = a.x * lw[c * 2] + a.y * lw[c * 2 + 2] + a.z * lw[c * 2 + 4] + a.w * lw[c * 2 + 6];
    float p1 = a.x * lw[c * 2 + 1] + a.y * lw[c * 2 + 3] + a.z * lw[c * 2 + 5] + a.w * lw[c * 2 + 7];
#pragma unroll
    for (int o = 16; o > 0; o >>= 1) {
        p0 += __shfl_down_sync(0xFFFFFFFFu, p0, o);
        p1 += __shfl_down_sync(0xFFFFFFFFu, p1, o);
    }
    __shared__ float s0[2], s1[2];
    if (lane == 0) { s0[warp] = p0; s1[warp] = p1; }
    __syncthreads();
    if (t == 0) {
        out[node * 2 + 0] = s0[0] + s0[1] + lb[0];
        out[node * 2 + 1] = s1[0] + s1[1] + lb[1];
    }
}

// ---------------- bf16 tensor-core multi-panel GEMM (mma.sync) ----------------
// C[M, Nc] = sum_p A_p[M,K] @ B_p[K,Nc]   (raw fp32 out; no bias/act)
struct PanelArgs {
    const bf16* A[3];
    const bf16* B[3];
};

__global__ void __launch_bounds__(256, 2)
k_mma(PanelArgs args, int K, int Nc,
      float* __restrict__ Cf, int M)
{
    const int BK = 32;
    __shared__ bf16 As[128 * 40]; // row pitch 40 bf16 = 80B
    __shared__ bf16 Bs[32 * 72];  // row pitch 72 bf16 = 144B

    int tid = threadIdx.x;
    int lane = tid & 31, warp = tid >> 5;
    int wm = warp & 3, wn = warp >> 2;       // 4 x 2 warp grid
    int blockRow = blockIdx.y * 128;
    int blockCol = blockIdx.x * 64;

    int perP = K / BK;
    int nIter = 3 * perP;

    int aRow = tid >> 2;   // 0..63
    int aChunk = tid & 3;  // *8 bf16
    int bRow = tid >> 3;   // 0..31
    int bChunk = tid & 7;  // *8 bf16

    uint4 ra0, ra1, rb;
    auto load_tile = [&](int it) {
        int p = it / perP;
        int kk = (it - p * perP) * BK;
        const bf16* A = args.A[p];
        const bf16* B = args.B[p];
        int r0 = blockRow + aRow;
        int r1 = r0 + 64;
        ra0 = make_uint4(0, 0, 0, 0);
        ra1 = make_uint4(0, 0, 0, 0);
        if (r0 < M) ra0 = *(const uint4*)(A + (size_t)r0 * K + kk + aChunk * 8);
        if (r1 < M) ra1 = *(const uint4*)(A + (size_t)r1 * K + kk + aChunk * 8);
        rb = *(const uint4*)(B + (size_t)(kk + bRow) * Nc + blockCol + bChunk * 8);
    };

    float c[2][4][4];
#pragma unroll
    for (int mt = 0; mt < 2; mt++)
#pragma unroll
        for (int nt = 0; nt < 4; nt++)
#pragma unroll
            for (int q = 0; q < 4; q++) c[mt][nt][q] = 0.f;

    load_tile(0);
#pragma unroll 1
    for (int it = 0; it < nIter; it++) {
        *(uint4*)&As[aRow * 40 + aChunk * 8] = ra0;
        *(uint4*)&As[(aRow + 64) * 40 + aChunk * 8] = ra1;
        *(uint4*)&Bs[bRow * 72 + bChunk * 8] = rb;
        __syncthreads();
        if (it + 1 < nIter) load_tile(it + 1);

#pragma unroll
        for (int ks = 0; ks < 2; ks++) {
            uint32_t af[2][4], bfr[2][4];
#pragma unroll
            for (int mt = 0; mt < 2; mt++) {
                int row = wm * 32 + mt * 16 + (lane & 15);
                int col = ks * 16 + (lane >> 4) * 8;
                uint32_t addr = (uint32_t)__cvta_generic_to_shared(&As[row * 40 + col]);
                asm volatile(
                    "ldmatrix.sync.aligned.m8n8.x4.shared.b16 {%0,%1,%2,%3}, [%4];"
                    : "=r"(af[mt][0]), "=r"(af[mt][1]), "=r"(af[mt][2]), "=r"(af[mt][3])
                    : "r"(addr));
            }
#pragma unroll
            for (int bt = 0; bt < 2; bt++) {
                int row = ks * 16 + (lane & 15);
                int col = wn * 32 + bt * 16 + (lane >> 4) * 8;
                uint32_t addr = (uint32_t)__cvta_generic_to_shared(&Bs[row * 72 + col]);
                asm volatile(
                    "ldmatrix.sync.aligned.m8n8.x4.trans.shared.b16 {%0,%1,%2,%3}, [%4];"
                    : "=r"(bfr[bt][0]), "=r"(bfr[bt][1]), "=r"(bfr[bt][2]), "=r"(bfr[bt][3])
                    : "r"(addr));
            }
#pragma unroll
            for (int mt = 0; mt < 2; mt++)
#pragma unroll
                for (int nt = 0; nt < 4; nt++) {
                    const uint32_t b0 = bfr[nt >> 1][(nt & 1) * 2];
                    const uint32_t b1 = bfr[nt >> 1][(nt & 1) * 2 + 1];
                    asm volatile(
                        "mma.sync.aligned.m16n8k16.row.col.f32.bf16.bf16.f32 "
                        "{%0,%1,%2,%3}, {%4,%5,%6,%7}, {%8,%9}, {%0,%1,%2,%3};"
                        : "+f"(c[mt][nt][0]), "+f"(c[mt][nt][1]),
                          "+f"(c[mt][nt][2]), "+f"(c[mt][nt][3])
                        : "r"(af[mt][0]), "r"(af[mt][1]), "r"(af[mt][2]), "r"(af[mt][3]),
                          "r"(b0), "r"(b1));
                }
        }
        __syncthreads();
    }

    // epilogue: raw fp32
#pragma unroll
    for (int mt = 0; mt < 2; mt++) {
#pragma unroll
        for (int half = 0; half < 2; half++) {
            int row = blockRow + wm * 32 + mt * 16 + half * 8 + (lane >> 2);
            if (row >= M) continue;
#pragma unroll
            for (int nt = 0; nt < 4; nt++) {
                int col = blockCol + wn * 32 + nt * 8 + (lane & 3) * 2;
                float2 f2;
                f2.x = c[mt][nt][half * 2 + 0];
                f2.y = c[mt][nt][half * 2 + 1];
                *(float2*)&Cf[(size_t)row * Nc + col] = f2;
            }
        }
    }
}

// ---------------- launch ----------------
extern "C" void kernel_launch(void* const* d_in, const int* in_sizes, int n_in,
                              void* d_out, int out_size) {
    (void)in_sizes; (void)n_in; (void)out_size;
    const float* x   = (const float*)d_in[0];
    const float* x1  = (const float*)d_in[1];
    const int*   ei  = (const int*)d_in[2];
    const int*   src = ei;
    const int*   dst = ei + EE;
    const float* gw0 = (const float*)d_in[3];
    const float* gb0 = (const float*)d_in[4];
    const float* gw1 = (const float*)d_in[5];
    const float* gb1 = (const float*)d_in[6];
    const float* wl0 = (const float*)d_in[7];
    const float* bl0 = (const float*)d_in[8];
    const float* wr0 = (const float*)d_in[9];
    const float* wl1 = (const float*)d_in[10];
    const float* bl1 = (const float*)d_in[11];
    const float* wr1 = (const float*)d_in[12];
    const float* lw  = (const float*)d_in[13];
    const float* lb  = (const float*)d_in[14];
    float* out = (float*)d_out;

    float *p_P1, *p_P2;
    cudaGetSymbolAddress((void**)&p_P1, d_P1);
    cudaGetSymbolAddress((void**)&p_P2, d_P2);

    bf16 *p_h1h, *p_h1l, *p_hch, *p_hcl, *p_h2h, *p_h2l;
    cudaGetSymbolAddress((void**)&p_h1h, d_h1h);
    cudaGetSymbolAddress((void**)&p_h1l, d_h1l);
    cudaGetSymbolAddress((void**)&p_hch, d_hch);
    cudaGetSymbolAddress((void**)&p_hcl, d_hcl);
    cudaGetSymbolAddress((void**)&p_h2h, d_h2h);
    cudaGetSymbolAddress((void**)&p_h2l, d_h2l);

    bf16 *p_gw1h, *p_gw1l, *p_w0h, *p_w0l, *p_w1h, *p_w1l;
    cudaGetSymbolAddress((void**)&p_gw1h, d_gw1h);
    cudaGetSymbolAddress((void**)&p_gw1l, d_gw1l);
    cudaGetSymbolAddress((void**)&p_w0h, d_w0h);
    cudaGetSymbolAddress((void**)&p_w0l, d_w0l);
    cudaGetSymbolAddress((void**)&p_w1h, d_w1h);
    cudaGetSymbolAddress((void**)&p_w1l, d_w1l);

    // CSR build + degrees
    k_zero_cnt<<<(NN + 255) / 256, 256>>>();
    k_count<<<(EE + 255) / 256, 256>>>(dst);
    k_scan1<<<NB_SCAN, 1024>>>();
    k_scan2<<<1, 32>>>();
    k_scan3<<<(NN + 1 + 255) / 256, 256>>>();
    k_fill<<<(EE + 255) / 256, 256>>>(src, dst);

    // weight splits (pack SAGE layers as [Wl | Wr] with pitch 512)
    k_split_w<<<(HH * HH + 255) / 256, 256>>>(gw1, p_gw1h, p_gw1l, HH * HH, HH, 0);
    k_split_w<<<(FH * HH + 255) / 256, 256>>>(wl0, p_w0h, p_w0l, FH * HH, 512, 0);
    k_split_w<<<(FH * HH + 255) / 256, 256>>>(wr0, p_w0h, p_w0l, FH * HH, 512, 256);
    k_split_w<<<(HH * HH + 255) / 256, 256>>>(wl1, p_w1h, p_w1l, HH * HH, 512, 0);
    k_split_w<<<(HH * HH + 255) / 256, 256>>>(wr1, p_w1h, p_w1l, HH * HH, 512, 256);

    // x -> hcat cols 0..63 (hi/lo)
    k_split_x<<<(NN * FF + 255) / 256, 256>>>(x);

    // GIN layer 0 (K = 1): g1 then h1 = tanh(g1*w0+b0) hi/lo
    k_gin0_agg<<<(NN + 255) / 256, 256>>>(x1);
    k_gin0_act<<<(NN * HH + 255) / 256, 256>>>(gw0, gb0);

    // GIN layer 1: P1 = h1 @ gw1; h1b = tanh(P1_self + agg(P1) + gb1) -> hcat cols 64..319
    {
        PanelArgs pa;
        pa.A[0] = p_h1h; pa.B[0] = p_gw1h;
        pa.A[1] = p_h1l; pa.B[1] = p_gw1h;
        pa.A[2] = p_h1h; pa.B[2] = p_gw1l;
        k_mma<<<dim3(HH / 64, MBLK), 256>>>(pa, HH, HH, p_P1, NN);
    }
    k_comb_gin<<<NN, 64>>>(p_P1, gb1);

    // SAGE layer 0: P2 = hcat @ [Wl0|Wr0]; h2 = relu(agg(P2l)/deg + bl0 + P2r_self)
    {
        PanelArgs pa;
        pa.A[0] = p_hch; pa.B[0] = p_w0h;
        pa.A[1] = p_hcl; pa.B[1] = p_w0h;
        pa.A[2] = p_hch; pa.B[2] = p_w0l;
        k_mma<<<dim3(512 / 64, MBLK), 256>>>(pa, FH, 512, p_P2, NN);
    }
    k_comb_sage<<<NN, 64>>>(p_P2, bl0, p_h2h, p_h2l);

    // SAGE layer 1 + output head
    {
        PanelArgs pa;
        pa.A[0] = p_h2h; pa.B[0] = p_w1h;
        pa.A[1] = p_h2l; pa.B[1] = p_w1h;
        pa.A[2] = p_h2h; pa.B[2] = p_w1l;
        k_mma<<<dim3(512 / 64, MBLK), 256>>>(pa, HH, 512, p_P2, NN);
    }
    k_comb_sage_out<<<NN, 64>>>(p_P2, bl1, lw, lb, out);
}

// round 5
// speedup vs baseline: 1.8174x; 1.2304x over previous
#include <cuda_runtime.h>
#include <cuda_bf16.h>
#include <math.h>
#include <stdint.h>

// Problem constants
static const int NN = 50000;
static const int FF = 64;
static const int HH = 256;
static const int EE = 1600000;
static const int FH = 320;                     // FF + HH
static const int NB_SCAN = (NN + 1023) / 1024; // 49
static const int MBLK = (NN + 127) / 128;      // 391

typedef __nv_bfloat16 bf16;
typedef __nv_bfloat162 bf162;

// ---------------- scratch (__device__ globals; allocation-free) ----------------
__device__ int   d_cnt[NN];
__device__ int   d_rowptr[NN + 1];
__device__ int   d_fill[NN];
__device__ int   d_col[EE];
__device__ int   d_bsum[64];
__device__ float d_deg[NN];
__device__ float d_g1[NN];
// bf16 hi/lo GEMM A operands
__device__ __align__(16) bf16 d_h1h[NN * HH];   // tanh(gin0) hi
__device__ __align__(16) bf16 d_h1l[NN * HH];   // tanh(gin0) lo
__device__ __align__(16) bf16 d_hch[NN * FH];   // [x | h1b] hi
__device__ __align__(16) bf16 d_hcl[NN * FH];   // [x | h1b] lo
__device__ __align__(16) bf16 d_h2h[NN * HH];   // relu(sage0) hi
__device__ __align__(16) bf16 d_h2l[NN * HH];   // relu(sage0) lo
// fp32 projection outputs (Pl = gathered panel, Pr = self panel)
__device__ __align__(16) float d_Pl[NN * HH];   // [N,256]
__device__ __align__(16) float d_Pr[NN * HH];   // [N,256]
// bf16 hi/lo weights
__device__ __align__(16) bf16 d_gw1h[HH * HH];       // [256,256]
__device__ __align__(16) bf16 d_gw1l[HH * HH];
__device__ __align__(16) bf16 d_w0h[FH * 2 * HH];    // [320,512] = [Wl0|Wr0]
__device__ __align__(16) bf16 d_w0l[FH * 2 * HH];
__device__ __align__(16) bf16 d_w1h[HH * 2 * HH];    // [256,512] = [Wl1|Wr1]
__device__ __align__(16) bf16 d_w1l[HH * 2 * HH];

// ---------------- CSR build ----------------
__global__ void k_zero_cnt() {
    int i = blockIdx.x * blockDim.x + threadIdx.x;
    if (i < NN) d_cnt[i] = 0;
}

__global__ void k_count(const int* __restrict__ dst) {
    int e = blockIdx.x * blockDim.x + threadIdx.x;
    if (e < EE) atomicAdd(&d_cnt[dst[e]], 1);
}

__global__ void k_scan1() {
    __shared__ int sh[1024];
    int tid = threadIdx.x;
    int i = blockIdx.x * 1024 + tid;
    int v = (i < NN) ? d_cnt[i] : 0;
    sh[tid] = v;
    __syncthreads();
#pragma unroll
    for (int off = 1; off < 1024; off <<= 1) {
        int t = (tid >= off) ? sh[tid - off] : 0;
        __syncthreads();
        sh[tid] += t;
        __syncthreads();
    }
    if (i < NN) d_rowptr[i] = sh[tid] - v; // exclusive
    if (tid == 1023) d_bsum[blockIdx.x] = sh[1023];
}

__global__ void k_scan2() {
    if (threadIdx.x == 0 && blockIdx.x == 0) {
        int run = 0;
        for (int b = 0; b < NB_SCAN; b++) {
            int t = d_bsum[b];
            d_bsum[b] = run;
            run += t;
        }
    }
}

__global__ void k_scan3() {
    int i = blockIdx.x * blockDim.x + threadIdx.x;
    if (i < NN) {
        int r = d_rowptr[i] + d_bsum[i >> 10];
        d_rowptr[i] = r;
        d_fill[i] = r;
        float c = (float)d_cnt[i];
        d_deg[i] = fmaxf(c, 1.0f);
    } else if (i == NN) {
        d_rowptr[NN] = EE;
    }
}

__global__ void k_fill(const int* __restrict__ src, const int* __restrict__ dst) {
    int e = blockIdx.x * blockDim.x + threadIdx.x;
    if (e < EE) {
        int pos = atomicAdd(&d_fill[dst[e]], 1);
        d_col[pos] = src[e];
    }
}

// ---------------- split helpers ----------------
__device__ __forceinline__ void split2(float v, bf16& h, bf16& l) {
    h = __float2bfloat16(v);
    l = __float2bfloat16(v - __bfloat162float(h));
}

// W [K, 256] row-major -> Wh/Wl [K, pitch] with column offset (for [Wl|Wr] packing)
__global__ void k_split_w(const float* __restrict__ W, bf16* __restrict__ Wh,
                          bf16* __restrict__ Wl, int n, int pitch, int coloff) {
    int i = blockIdx.x * blockDim.x + threadIdx.x;
    if (i >= n) return;
    int k = i >> 8;
    int c = i & 255;
    bf16 h, l;
    split2(W[i], h, l);
    size_t o = (size_t)k * pitch + coloff + c;
    Wh[o] = h; Wl[o] = l;
}

// x [N,64] -> hch/hcl columns 0..63 (pitch 320)
__global__ void k_split_x(const float* __restrict__ x) {
    int i = blockIdx.x * blockDim.x + threadIdx.x;
    if (i >= NN * FF) return;
    int r = i >> 6;
    int c = i & 63;
    bf16 h, l;
    split2(x[i], h, l);
    size_t o = (size_t)r * FH + c;
    d_hch[o] = h; d_hcl[o] = l;
}

// ---------------- GIN0 (K = 1) ----------------
__global__ void k_gin0_agg(const float* __restrict__ x1) {
    int i = blockIdx.x * blockDim.x + threadIdx.x;
    if (i >= NN) return;
    int beg = d_rowptr[i], end = d_rowptr[i + 1];
    float s = x1[i]; // self (eps = 0)
    for (int j = beg; j < end; j++) s += x1[d_col[j]];
    d_g1[i] = s;
}

__global__ void k_gin0_act(const float* __restrict__ w0, const float* __restrict__ b0) {
    int idx = blockIdx.x * blockDim.x + threadIdx.x;
    if (idx >= NN * HH) return;
    int i = idx >> 8;
    int c = idx & 255;
    float v = tanhf(d_g1[i] * w0[c] + b0[c]);
    bf16 h, l;
    split2(v, h, l);
    d_h1h[idx] = h;
    d_h1l[idx] = l;
}

// ---------------- fused gather + combine kernels ----------------
// 1 block (64 threads) per node; thread t handles float4 cols [4t, 4t+4).

__device__ __forceinline__ float4 gather_sum(const float4* __restrict__ P4,
                                             int beg, int end, int t) {
    float4 a = make_float4(0.f, 0.f, 0.f, 0.f);
    int j = beg;
    for (; j + 1 < end; j += 2) {
        int s0 = d_col[j], s1 = d_col[j + 1];
        float4 v0 = P4[(size_t)s0 * 64 + t];
        float4 v1 = P4[(size_t)s1 * 64 + t];
        a.x += v0.x + v1.x; a.y += v0.y + v1.y;
        a.z += v0.z + v1.z; a.w += v0.w + v1.w;
    }
    if (j < end) {
        float4 v = P4[(size_t)d_col[j] * 64 + t];
        a.x += v.x; a.y += v.y; a.z += v.z; a.w += v.w;
    }
    return a;
}

__device__ __forceinline__ void store_hl(bf16* __restrict__ oh, bf16* __restrict__ ol,
                                         size_t o, float4 a) {
    bf16 h0, l0, h1, l1;
    bf162 ph, pl;
    split2(a.x, h0, l0); split2(a.y, h1, l1);
    ph.x = h0; ph.y = h1; pl.x = l0; pl.y = l1;
    *(bf162*)&oh[o] = ph; *(bf162*)&ol[o] = pl;
    split2(a.z, h0, l0); split2(a.w, h1, l1);
    ph.x = h0; ph.y = h1; pl.x = l0; pl.y = l1;
    *(bf162*)&oh[o + 2] = ph; *(bf162*)&ol[o + 2] = pl;
}

// GIN1: out = tanh(P[node] + sum_nbr P[nbr] + b); write hi/lo into hcat cols 64..319
__global__ void k_comb_gin(const float* __restrict__ P,
                           const float* __restrict__ bias) {
    int node = blockIdx.x;
    int t = threadIdx.x;
    const float4* P4 = (const float4*)P;
    float4 a = gather_sum(P4, d_rowptr[node], d_rowptr[node + 1], t);
    float4 s = P4[(size_t)node * 64 + t];
    float4 bv = *(const float4*)&bias[t * 4];
    a.x = tanhf(a.x + s.x + bv.x); a.y = tanhf(a.y + s.y + bv.y);
    a.z = tanhf(a.z + s.z + bv.z); a.w = tanhf(a.w + s.w + bv.w);
    store_hl(d_hch, d_hcl, (size_t)node * FH + 64 + t * 4, a);
}

// SAGE: out = relu(sum_nbr Pl[nbr]/deg + b + Pr[node]); write h2 hi/lo
__global__ void k_comb_sage(const float* __restrict__ Pl,
                            const float* __restrict__ Pr,
                            const float* __restrict__ bias,
                            bf16* __restrict__ oh, bf16* __restrict__ ol) {
    int node = blockIdx.x;
    int t = threadIdx.x;
    const float4* Pl4 = (const float4*)Pl;
    const float4* Pr4 = (const float4*)Pr;
    float4 a = gather_sum(Pl4, d_rowptr[node], d_rowptr[node + 1], t);
    float inv = 1.0f / d_deg[node];
    float4 r = Pr4[(size_t)node * 64 + t];
    float4 bv = *(const float4*)&bias[t * 4];
    a.x = fmaxf(a.x * inv + bv.x + r.x, 0.f);
    a.y = fmaxf(a.y * inv + bv.y + r.y, 0.f);
    a.z = fmaxf(a.z * inv + bv.z + r.z, 0.f);
    a.w = fmaxf(a.w * inv + bv.w + r.w, 0.f);
    store_hl(oh, ol, (size_t)node * HH + t * 4, a);
}

// SAGE final: combine + fused output head: out[node] = v . lw + lb  (256 -> 2)
__global__ void k_comb_sage_out(const float* __restrict__ Pl,
                                const float* __restrict__ Pr,
                                const float* __restrict__ bias,
                                const float* __restrict__ lw,
                                const float* __restrict__ lb,
                                float* __restrict__ out) {
    int node = blockIdx.x;
    int t = threadIdx.x;
    int lane = t & 31, warp = t >> 5;
    const float4* Pl4 = (const float4*)Pl;
    const float4* Pr4 = (const float4*)Pr;
    float4 a = gather_sum(Pl4, d_rowptr[node], d_rowptr[node + 1], t);
    float inv = 1.0f / d_deg[node];
    float4 r = Pr4[(size_t)node * 64 + t];
    float4 bv = *(const float4*)&bias[t * 4];
    a.x = fmaxf(a.x * inv + bv.x + r.x, 0.f);
    a.y = fmaxf(a.y * inv + bv.y + r.y, 0.f);
    a.z = fmaxf(a.z * inv + bv.z + r.z, 0.f);
    a.w = fmaxf(a.w * inv + bv.w + r.w, 0.f);
    int c = t * 4;
    float p0 = a.x * lw[c * 2] + a.y * lw[c * 2 + 2] + a.z * lw[c * 2 + 4] + a.w * lw[c * 2 + 6];
    float p1 = a.x * lw[c * 2 + 1] + a.y * lw[c * 2 + 3] + a.z * lw[c * 2 + 5] + a.w * lw[c * 2 + 7];
#pragma unroll
    for (int o = 16; o > 0; o >>= 1) {
        p0 += __shfl_down_sync(0xFFFFFFFFu, p0, o);
        p1 += __shfl_down_sync(0xFFFFFFFFu, p1, o);
    }
    __shared__ float s0[2], s1[2];
    if (lane == 0) { s0[warp] = p0; s1[warp] = p1; }
    __syncthreads();
    if (t == 0) {
        out[node * 2 + 0] = s0[0] + s0[1] + lb[0];
        out[node * 2 + 1] = s1[0] + s1[1] + lb[1];
    }
}

// ---------------- bf16 tensor-core multi-panel GEMM (mma.sync + cp.async) ----------------
// C[M, Nc] = sum_p A_p[M,K] @ B_p[K,Nc]   (raw fp32 out)
// Nc = 256: all cols to C0 (pitch 256). Nc = 512: cols 0..255 -> C0, 256..511 -> C1.
struct PanelArgs {
    const bf16* A[3];
    const bf16* B[3];
};

#define CP_ASYNC16(dst, src, sz) \
    asm volatile("cp.async.cg.shared.global [%0], [%1], 16, %2;" \
                 :: "r"(dst), "l"(src), "r"(sz))
#define CP_COMMIT() asm volatile("cp.async.commit_group;")
#define CP_WAIT1()  asm volatile("cp.async.wait_group 1;")
#define CP_WAIT0()  asm volatile("cp.async.wait_group 0;")

// As pitch 40 bf16 (80B), Bs pitch 136 bf16 (272B)
static const int APITCH = 40;
static const int BPITCH = 136;

__global__ void __launch_bounds__(256, 2)
k_mma(PanelArgs args, int K, int Nc,
      float* __restrict__ C0, float* __restrict__ C1, int M)
{
    __shared__ bf16 As[2][128 * APITCH];
    __shared__ bf16 Bs[2][32 * BPITCH];

    const int tid = threadIdx.x;
    const int lane = tid & 31, warp = tid >> 5;
    const int wm = warp >> 1, wn = warp & 1;  // 4 x 2 warp grid, 32x64 per warp
    const int blockRow = blockIdx.y * 128;
    const int blockCol = blockIdx.x * 128;

    const int perP = K >> 5;   // BK = 32
    const int nIter = 3 * perP;

    // A: 128 rows x 32 cols = 512 x 16B chunks; thread handles idx = tid + i*256
    // B: 32 rows x 128 cols = 512 x 16B chunks
    uint32_t as_base = (uint32_t)__cvta_generic_to_shared(&As[0][0]);
    uint32_t bs_base = (uint32_t)__cvta_generic_to_shared(&Bs[0][0]);

    auto prefetch = [&](int it) {
        int st = it & 1;
        int p = it / perP;
        int kk = (it - p * perP) << 5;
        const bf16* A = args.A[p];
        const bf16* B = args.B[p];
#pragma unroll
        for (int i = 0; i < 2; i++) {
            int idx = tid + i * 256;
            int row = idx >> 2, ch = idx & 3;
            int gr = blockRow + row;
            int ok = (gr < M) ? 16 : 0;
            const bf16* src = A + (size_t)(ok ? gr : 0) * K + kk + ch * 8;
            uint32_t dst = as_base + st * (128 * APITCH * 2) + (row * APITCH + ch * 8) * 2;
            CP_ASYNC16(dst, src, ok);
        }
#pragma unroll
        for (int i = 0; i < 2; i++) {
            int idx = tid + i * 256;
            int row = idx >> 4, ch = idx & 15;
            const bf16* src = B + (size_t)(kk + row) * Nc + blockCol + ch * 8;
            uint32_t dst = bs_base + st * (32 * BPITCH * 2) + (row * BPITCH + ch * 8) * 2;
            CP_ASYNC16(dst, src, 16);
        }
    };

    float c[2][8][4];
#pragma unroll
    for (int mt = 0; mt < 2; mt++)
#pragma unroll
        for (int nt = 0; nt < 8; nt++)
#pragma unroll
            for (int q = 0; q < 4; q++) c[mt][nt][q] = 0.f;

    prefetch(0);
    CP_COMMIT();

#pragma unroll 1
    for (int it = 0; it < nIter; it++) {
        if (it + 1 < nIter) {
            prefetch(it + 1);
            CP_COMMIT();
            CP_WAIT1();
        } else {
            CP_WAIT0();
        }
        __syncthreads();

        const int st = it & 1;
        const bf16* as = As[st];
        const bf16* bs = Bs[st];
#pragma unroll
        for (int ks = 0; ks < 2; ks++) {
            uint32_t af[2][4], bfr[4][4];
#pragma unroll
            for (int mt = 0; mt < 2; mt++) {
                int row = wm * 32 + mt * 16 + (lane & 15);
                int col = ks * 16 + (lane >> 4) * 8;
                uint32_t addr = (uint32_t)__cvta_generic_to_shared(&as[row * APITCH + col]);
                asm volatile(
                    "ldmatrix.sync.aligned.m8n8.x4.shared.b16 {%0,%1,%2,%3}, [%4];"
                    : "=r"(af[mt][0]), "=r"(af[mt][1]), "=r"(af[mt][2]), "=r"(af[mt][3])
                    : "r"(addr));
            }
#pragma unroll
            for (int bt = 0; bt < 4; bt++) {
                int row = ks * 16 + (lane & 15);
                int col = wn * 64 + bt * 16 + (lane >> 4) * 8;
                uint32_t addr = (uint32_t)__cvta_generic_to_shared(&bs[row * BPITCH + col]);
                asm volatile(
                    "ldmatrix.sync.aligned.m8n8.x4.trans.shared.b16 {%0,%1,%2,%3}, [%4];"
                    : "=r"(bfr[bt][0]), "=r"(bfr[bt][1]), "=r"(bfr[bt][2]), "=r"(bfr[bt][3])
                    : "r"(addr));
            }
#pragma unroll
            for (int mt = 0; mt < 2; mt++)
#pragma unroll
                for (int nt = 0; nt < 8; nt++) {
                    const uint32_t b0 = bfr[nt >> 1][(nt & 1) * 2];
                    const uint32_t b1 = bfr[nt >> 1][(nt & 1) * 2 + 1];
                    asm volatile(
                        "mma.sync.aligned.m16n8k16.row.col.f32.bf16.bf16.f32 "
                        "{%0,%1,%2,%3}, {%4,%5,%6,%7}, {%8,%9}, {%0,%1,%2,%3};"
                        : "+f"(c[mt][nt][0]), "+f"(c[mt][nt][1]),
                          "+f"(c[mt][nt][2]), "+f"(c[mt][nt][3])
                        : "r"(af[mt][0]), "r"(af[mt][1]), "r"(af[mt][2]), "r"(af[mt][3]),
                          "r"(b0), "r"(b1));
                }
        }
        __syncthreads();
    }

    // epilogue
#pragma unroll
    for (int mt = 0; mt < 2; mt++) {
#pragma unroll
        for (int half = 0; half < 2; half++) {
            int row = blockRow + wm * 32 + mt * 16 + half * 8 + (lane >> 2);
            if (row >= M) continue;
#pragma unroll
            for (int nt = 0; nt < 8; nt++) {
                int gcol = blockCol + wn * 64 + nt * 8 + (lane & 3) * 2;
                float2 f2;
                f2.x = c[mt][nt][half * 2 + 0];
                f2.y = c[mt][nt][half * 2 + 1];
                float* Cp = (gcol < 256) ? C0 : C1;
                int cc = gcol & 255;
                *(float2*)&Cp[(size_t)row * 256 + cc] = f2;
            }
        }
    }
}

// ---------------- launch ----------------
extern "C" void kernel_launch(void* const* d_in, const int* in_sizes, int n_in,
                              void* d_out, int out_size) {
    (void)in_sizes; (void)n_in; (void)out_size;
    const float* x   = (const float*)d_in[0];
    const float* x1  = (const float*)d_in[1];
    const int*   ei  = (const int*)d_in[2];
    const int*   src = ei;
    const int*   dst = ei + EE;
    const float* gw0 = (const float*)d_in[3];
    const float* gb0 = (const float*)d_in[4];
    const float* gw1 = (const float*)d_in[5];
    const float* gb1 = (const float*)d_in[6];
    const float* wl0 = (const float*)d_in[7];
    const float* bl0 = (const float*)d_in[8];
    const float* wr0 = (const float*)d_in[9];
    const float* wl1 = (const float*)d_in[10];
    const float* bl1 = (const float*)d_in[11];
    const float* wr1 = (const float*)d_in[12];
    const float* lw  = (const float*)d_in[13];
    const float* lb  = (const float*)d_in[14];
    float* out = (float*)d_out;

    float *p_Pl, *p_Pr;
    cudaGetSymbolAddress((void**)&p_Pl, d_Pl);
    cudaGetSymbolAddress((void**)&p_Pr, d_Pr);

    bf16 *p_h1h, *p_h1l, *p_hch, *p_hcl, *p_h2h, *p_h2l;
    cudaGetSymbolAddress((void**)&p_h1h, d_h1h);
    cudaGetSymbolAddress((void**)&p_h1l, d_h1l);
    cudaGetSymbolAddress((void**)&p_hch, d_hch);
    cudaGetSymbolAddress((void**)&p_hcl, d_hcl);
    cudaGetSymbolAddress((void**)&p_h2h, d_h2h);
    cudaGetSymbolAddress((void**)&p_h2l, d_h2l);

    bf16 *p_gw1h, *p_gw1l, *p_w0h, *p_w0l, *p_w1h, *p_w1l;
    cudaGetSymbolAddress((void**)&p_gw1h, d_gw1h);
    cudaGetSymbolAddress((void**)&p_gw1l, d_gw1l);
    cudaGetSymbolAddress((void**)&p_w0h, d_w0h);
    cudaGetSymbolAddress((void**)&p_w0l, d_w0l);
    cudaGetSymbolAddress((void**)&p_w1h, d_w1h);
    cudaGetSymbolAddress((void**)&p_w1l, d_w1l);

    // CSR build + degrees
    k_zero_cnt<<<(NN + 255) / 256, 256>>>();
    k_count<<<(EE + 255) / 256, 256>>>(dst);
    k_scan1<<<NB_SCAN, 1024>>>();
    k_scan2<<<1, 32>>>();
    k_scan3<<<(NN + 1 + 255) / 256, 256>>>();
    k_fill<<<(EE + 255) / 256, 256>>>(src, dst);

    // weight splits (pack SAGE layers as [Wl | Wr] with pitch 512)
    k_split_w<<<(HH * HH + 255) / 256, 256>>>(gw1, p_gw1h, p_gw1l, HH * HH, HH, 0);
    k_split_w<<<(FH * HH + 255) / 256, 256>>>(wl0, p_w0h, p_w0l, FH * HH, 512, 0);
    k_split_w<<<(FH * HH + 255) / 256, 256>>>(wr0, p_w0h, p_w0l, FH * HH, 512, 256);
    k_split_w<<<(HH * HH + 255) / 256, 256>>>(wl1, p_w1h, p_w1l, HH * HH, 512, 0);
    k_split_w<<<(HH * HH + 255) / 256, 256>>>(wr1, p_w1h, p_w1l, HH * HH, 512, 256);

    // x -> hcat cols 0..63 (hi/lo)
    k_split_x<<<(NN * FF + 255) / 256, 256>>>(x);

    // GIN layer 0 (K = 1)
    k_gin0_agg<<<(NN + 255) / 256, 256>>>(x1);
    k_gin0_act<<<(NN * HH + 255) / 256, 256>>>(gw0, gb0);

    // GIN layer 1: Pl = h1 @ gw1; h1b = tanh(Pl_self + agg(Pl) + gb1) -> hcat cols 64..319
    {
        PanelArgs pa;
        pa.A[0] = p_h1h; pa.B[0] = p_gw1h;
        pa.A[1] = p_h1l; pa.B[1] = p_gw1h;
        pa.A[2] = p_h1h; pa.B[2] = p_gw1l;
        k_mma<<<dim3(HH / 128, MBLK), 256>>>(pa, HH, HH, p_Pl, nullptr, NN);
    }
    k_comb_gin<<<NN, 64>>>(p_Pl, gb1);

    // SAGE layer 0
    {
        PanelArgs pa;
        pa.A[0] = p_hch; pa.B[0] = p_w0h;
        pa.A[1] = p_hcl; pa.B[1] = p_w0h;
        pa.A[2] = p_hch; pa.B[2] = p_w0l;
        k_mma<<<dim3(512 / 128, MBLK), 256>>>(pa, FH, 512, p_Pl, p_Pr, NN);
    }
    k_comb_sage<<<NN, 64>>>(p_Pl, p_Pr, bl0, p_h2h, p_h2l);

    // SAGE layer 1 + output head
    {
        PanelArgs pa;
        pa.A[0] = p_h2h; pa.B[0] = p_w1h;
        pa.A[1] = p_h2l; pa.B[1] = p_w1h;
        pa.A[2] = p_h2h; pa.B[2] = p_w1l;
        k_mma<<<dim3(512 / 128, MBLK), 256>>>(pa, HH, 512, p_Pl, p_Pr, NN);
    }
    k_comb_sage_out<<<NN, 64>>>(p_Pl, p_Pr, bl1, lw, lb, out);
}

// round 6
// speedup vs baseline: 1.9750x; 1.0867x over previous
#include <cuda_runtime.h>
#include <cuda_bf16.h>
#include <cuda_fp16.h>
#include <math.h>
#include <stdint.h>

// Problem constants
static const int NN = 50000;
static const int FF = 64;
static const int HH = 256;
static const int EE = 1600000;
static const int FH = 320;                     // FF + HH
static const int NB_SCAN = (NN + 1023) / 1024; // 49
static const int MBLK = (NN + 127) / 128;      // 391

typedef __nv_bfloat16 bf16;
typedef __nv_bfloat162 bf162;

// ---------------- scratch (__device__ globals; allocation-free) ----------------
__device__ int   d_cnt[NN];
__device__ int   d_rowptr[NN + 1];
__device__ int   d_fill[NN];
__device__ int   d_col[EE];
__device__ int   d_bsum[64];
__device__ float d_deg[NN];
__device__ float d_g1[NN];
// bf16 hi/lo GEMM A operands
__device__ __align__(16) bf16 d_h1h[NN * HH];   // tanh(gin0) hi
__device__ __align__(16) bf16 d_h1l[NN * HH];   // tanh(gin0) lo
__device__ __align__(16) bf16 d_hch[NN * FH];   // [x | h1b] hi
__device__ __align__(16) bf16 d_hcl[NN * FH];   // [x | h1b] lo
__device__ __align__(16) bf16 d_h2h[NN * HH];   // relu(sage0) hi
__device__ __align__(16) bf16 d_h2l[NN * HH];   // relu(sage0) lo
// fp16 projection outputs (Pl = gathered panel, Pr = self panel)
__device__ __align__(16) __half d_Pl[NN * HH];  // [N,256]
__device__ __align__(16) __half d_Pr[NN * HH];  // [N,256]
// bf16 hi/lo weights
__device__ __align__(16) bf16 d_gw1h[HH * HH];       // [256,256]
__device__ __align__(16) bf16 d_gw1l[HH * HH];
__device__ __align__(16) bf16 d_w0h[FH * 2 * HH];    // [320,512] = [Wl0|Wr0]
__device__ __align__(16) bf16 d_w0l[FH * 2 * HH];
__device__ __align__(16) bf16 d_w1h[HH * 2 * HH];    // [256,512] = [Wl1|Wr1]
__device__ __align__(16) bf16 d_w1l[HH * 2 * HH];

// ---------------- CSR build ----------------
__global__ void k_zero_cnt() {
    int i = blockIdx.x * blockDim.x + threadIdx.x;
    if (i < NN) d_cnt[i] = 0;
}

__global__ void k_count(const int* __restrict__ dst) {
    int e = blockIdx.x * blockDim.x + threadIdx.x;
    if (e < EE) atomicAdd(&d_cnt[dst[e]], 1);
}

__global__ void k_scan1() {
    __shared__ int sh[1024];
    int tid = threadIdx.x;
    int i = blockIdx.x * 1024 + tid;
    int v = (i < NN) ? d_cnt[i] : 0;
    sh[tid] = v;
    __syncthreads();
#pragma unroll
    for (int off = 1; off < 1024; off <<= 1) {
        int t = (tid >= off) ? sh[tid - off] : 0;
        __syncthreads();
        sh[tid] += t;
        __syncthreads();
    }
    if (i < NN) d_rowptr[i] = sh[tid] - v; // exclusive
    if (tid == 1023) d_bsum[blockIdx.x] = sh[1023];
}

__global__ void k_scan2() {
    if (threadIdx.x == 0 && blockIdx.x == 0) {
        int run = 0;
        for (int b = 0; b < NB_SCAN; b++) {
            int t = d_bsum[b];
            d_bsum[b] = run;
            run += t;
        }
    }
}

__global__ void k_scan3() {
    int i = blockIdx.x * blockDim.x + threadIdx.x;
    if (i < NN) {
        int r = d_rowptr[i] + d_bsum[i >> 10];
        d_rowptr[i] = r;
        d_fill[i] = r;
        float c = (float)d_cnt[i];
        d_deg[i] = fmaxf(c, 1.0f);
    } else if (i == NN) {
        d_rowptr[NN] = EE;
    }
}

__global__ void k_fill(const int* __restrict__ src, const int* __restrict__ dst) {
    int e = blockIdx.x * blockDim.x + threadIdx.x;
    if (e < EE) {
        int pos = atomicAdd(&d_fill[dst[e]], 1);
        d_col[pos] = src[e];
    }
}

// ---------------- split helpers ----------------
__device__ __forceinline__ void split2(float v, bf16& h, bf16& l) {
    h = __float2bfloat16(v);
    l = __float2bfloat16(v - __bfloat162float(h));
}

// W [K, 256] row-major -> Wh/Wl [K, pitch] with column offset (for [Wl|Wr] packing)
__global__ void k_split_w(const float* __restrict__ W, bf16* __restrict__ Wh,
                          bf16* __restrict__ Wl, int n, int pitch, int coloff) {
    int i = blockIdx.x * blockDim.x + threadIdx.x;
    if (i >= n) return;
    int k = i >> 8;
    int c = i & 255;
    bf16 h, l;
    split2(W[i], h, l);
    size_t o = (size_t)k * pitch + coloff + c;
    Wh[o] = h; Wl[o] = l;
}

// x [N,64] -> hch/hcl columns 0..63 (pitch 320)
__global__ void k_split_x(const float* __restrict__ x) {
    int i = blockIdx.x * blockDim.x + threadIdx.x;
    if (i >= NN * FF) return;
    int r = i >> 6;
    int c = i & 63;
    bf16 h, l;
    split2(x[i], h, l);
    size_t o = (size_t)r * FH + c;
    d_hch[o] = h; d_hcl[o] = l;
}

// ---------------- GIN0 (K = 1) ----------------
__global__ void k_gin0_agg(const float* __restrict__ x1) {
    int i = blockIdx.x * blockDim.x + threadIdx.x;
    if (i >= NN) return;
    int beg = d_rowptr[i], end = d_rowptr[i + 1];
    float s = x1[i]; // self (eps = 0)
    for (int j = beg; j < end; j++) s += x1[d_col[j]];
    d_g1[i] = s;
}

__global__ void k_gin0_act(const float* __restrict__ w0, const float* __restrict__ b0) {
    int idx = blockIdx.x * blockDim.x + threadIdx.x;
    if (idx >= NN * HH) return;
    int i = idx >> 8;
    int c = idx & 255;
    float v = tanhf(d_g1[i] * w0[c] + b0[c]);
    bf16 h, l;
    split2(v, h, l);
    d_h1h[idx] = h;
    d_h1l[idx] = l;
}

// ---------------- fused gather + combine kernels ----------------
// 1 block (64 threads) per node; thread t handles cols [4t, 4t+4).
// P rows are 256 fp16 = 64 x uint2 (8B) per row.

__device__ __forceinline__ void acc_u2(float4& a, uint2 u) {
    float2 f0 = __half22float2(*(__half2*)&u.x);
    float2 f1 = __half22float2(*(__half2*)&u.y);
    a.x += f0.x; a.y += f0.y; a.z += f1.x; a.w += f1.y;
}

__device__ __forceinline__ float4 gather_sum_h(const uint2* __restrict__ P2,
                                               int beg, int end, int t) {
    float4 a = make_float4(0.f, 0.f, 0.f, 0.f);
    int j = beg;
    for (; j + 3 < end; j += 4) {
        int s0 = d_col[j], s1 = d_col[j + 1], s2 = d_col[j + 2], s3 = d_col[j + 3];
        uint2 u0 = P2[(size_t)s0 * 64 + t];
        uint2 u1 = P2[(size_t)s1 * 64 + t];
        uint2 u2 = P2[(size_t)s2 * 64 + t];
        uint2 u3 = P2[(size_t)s3 * 64 + t];
        acc_u2(a, u0); acc_u2(a, u1); acc_u2(a, u2); acc_u2(a, u3);
    }
    for (; j < end; j++) {
        uint2 u = P2[(size_t)d_col[j] * 64 + t];
        acc_u2(a, u);
    }
    return a;
}

__device__ __forceinline__ float4 read_row_h(const uint2* __restrict__ P2,
                                             int node, int t) {
    uint2 u = P2[(size_t)node * 64 + t];
    float2 f0 = __half22float2(*(__half2*)&u.x);
    float2 f1 = __half22float2(*(__half2*)&u.y);
    return make_float4(f0.x, f0.y, f1.x, f1.y);
}

__device__ __forceinline__ void store_hl(bf16* __restrict__ oh, bf16* __restrict__ ol,
                                         size_t o, float4 a) {
    bf16 h0, l0, h1, l1;
    bf162 ph, pl;
    split2(a.x, h0, l0); split2(a.y, h1, l1);
    ph.x = h0; ph.y = h1; pl.x = l0; pl.y = l1;
    *(bf162*)&oh[o] = ph; *(bf162*)&ol[o] = pl;
    split2(a.z, h0, l0); split2(a.w, h1, l1);
    ph.x = h0; ph.y = h1; pl.x = l0; pl.y = l1;
    *(bf162*)&oh[o + 2] = ph; *(bf162*)&ol[o + 2] = pl;
}

// GIN1: out = tanh(P[node] + sum_nbr P[nbr] + b); write hi/lo into hcat cols 64..319
__global__ void k_comb_gin(const __half* __restrict__ P,
                           const float* __restrict__ bias) {
    int node = blockIdx.x;
    int t = threadIdx.x;
    const uint2* P2 = (const uint2*)P;
    float4 a = gather_sum_h(P2, d_rowptr[node], d_rowptr[node + 1], t);
    float4 s = read_row_h(P2, node, t);
    float4 bv = *(const float4*)&bias[t * 4];
    a.x = tanhf(a.x + s.x + bv.x); a.y = tanhf(a.y + s.y + bv.y);
    a.z = tanhf(a.z + s.z + bv.z); a.w = tanhf(a.w + s.w + bv.w);
    store_hl(d_hch, d_hcl, (size_t)node * FH + 64 + t * 4, a);
}

// SAGE: out = relu(sum_nbr Pl[nbr]/deg + b + Pr[node]); write h2 hi/lo
__global__ void k_comb_sage(const __half* __restrict__ Pl,
                            const __half* __restrict__ Pr,
                            const float* __restrict__ bias,
                            bf16* __restrict__ oh, bf16* __restrict__ ol) {
    int node = blockIdx.x;
    int t = threadIdx.x;
    const uint2* Pl2 = (const uint2*)Pl;
    const uint2* Pr2 = (const uint2*)Pr;
    float4 a = gather_sum_h(Pl2, d_rowptr[node], d_rowptr[node + 1], t);
    float inv = 1.0f / d_deg[node];
    float4 r = read_row_h(Pr2, node, t);
    float4 bv = *(const float4*)&bias[t * 4];
    a.x = fmaxf(a.x * inv + bv.x + r.x, 0.f);
    a.y = fmaxf(a.y * inv + bv.y + r.y, 0.f);
    a.z = fmaxf(a.z * inv + bv.z + r.z, 0.f);
    a.w = fmaxf(a.w * inv + bv.w + r.w, 0.f);
    store_hl(oh, ol, (size_t)node * HH + t * 4, a);
}

// SAGE final: combine + fused output head: out[node] = v . lw + lb  (256 -> 2)
__global__ void k_comb_sage_out(const __half* __restrict__ Pl,
                                const __half* __restrict__ Pr,
                                const float* __restrict__ bias,
                                const float* __restrict__ lw,
                                const float* __restrict__ lb,
                                float* __restrict__ out) {
    int node = blockIdx.x;
    int t = threadIdx.x;
    int lane = t & 31, warp = t >> 5;
    const uint2* Pl2 = (const uint2*)Pl;
    const uint2* Pr2 = (const uint2*)Pr;
    float4 a = gather_sum_h(Pl2, d_rowptr[node], d_rowptr[node + 1], t);
    float inv = 1.0f / d_deg[node];
    float4 r = read_row_h(Pr2, node, t);
    float4 bv = *(const float4*)&bias[t * 4];
    a.x = fmaxf(a.x * inv + bv.x + r.x, 0.f);
    a.y = fmaxf(a.y * inv + bv.y + r.y, 0.f);
    a.z = fmaxf(a.z * inv + bv.z + r.z, 0.f);
    a.w = fmaxf(a.w * inv + bv.w + r.w, 0.f);
    int c = t * 4;
    float p0 = a.x * lw[c * 2] + a.y * lw[c * 2 + 2] + a.z * lw[c * 2 + 4] + a.w * lw[c * 2 + 6];
    float p1 = a.x * lw[c * 2 + 1] + a.y * lw[c * 2 + 3] + a.z * lw[c * 2 + 5] + a.w * lw[c * 2 + 7];
#pragma unroll
    for (int o = 16; o > 0; o >>= 1) {
        p0 += __shfl_down_sync(0xFFFFFFFFu, p0, o);
        p1 += __shfl_down_sync(0xFFFFFFFFu, p1, o);
    }
    __shared__ float s0[2], s1[2];
    if (lane == 0) { s0[warp] = p0; s1[warp] = p1; }
    __syncthreads();
    if (t == 0) {
        out[node * 2 + 0] = s0[0] + s0[1] + lb[0];
        out[node * 2 + 1] = s1[0] + s1[1] + lb[1];
    }
}

// ---------------- bf16 tensor-core multi-panel GEMM (mma.sync + cp.async) ----------------
// C[M, Nc] = sum_p A_p[M,K] @ B_p[K,Nc]   (fp16 out)
// Nc = 256: all cols to C0 (pitch 256). Nc = 512: cols 0..255 -> C0, 256..511 -> C1.
struct PanelArgs {
    const bf16* A[3];
    const bf16* B[3];
};

#define CP_ASYNC16(dst, src, sz) \
    asm volatile("cp.async.cg.shared.global [%0], [%1], 16, %2;" \
                 :: "r"(dst), "l"(src), "r"(sz))
#define CP_COMMIT() asm volatile("cp.async.commit_group;")
#define CP_WAIT1()  asm volatile("cp.async.wait_group 1;")
#define CP_WAIT0()  asm volatile("cp.async.wait_group 0;")

// As pitch 40 bf16 (80B), Bs pitch 136 bf16 (272B)
static const int APITCH = 40;
static const int BPITCH = 136;

__global__ void __launch_bounds__(256, 2)
k_mma(PanelArgs args, int K, int Nc,
      __half* __restrict__ C0, __half* __restrict__ C1, int M)
{
    __shared__ bf16 As[2][128 * APITCH];
    __shared__ bf16 Bs[2][32 * BPITCH];

    const int tid = threadIdx.x;
    const int lane = tid & 31, warp = tid >> 5;
    const int wm = warp >> 1, wn = warp & 1;  // 4 x 2 warp grid, 32x64 per warp
    const int blockRow = blockIdx.y * 128;
    const int blockCol = blockIdx.x * 128;

    const int perP = K >> 5;   // BK = 32
    const int nIter = 3 * perP;

    uint32_t as_base = (uint32_t)__cvta_generic_to_shared(&As[0][0]);
    uint32_t bs_base = (uint32_t)__cvta_generic_to_shared(&Bs[0][0]);

    auto prefetch = [&](int it) {
        int st = it & 1;
        int p = it / perP;
        int kk = (it - p * perP) << 5;
        const bf16* A = args.A[p];
        const bf16* B = args.B[p];
#pragma unroll
        for (int i = 0; i < 2; i++) {
            int idx = tid + i * 256;
            int row = idx >> 2, ch = idx & 3;
            int gr = blockRow + row;
            int ok = (gr < M) ? 16 : 0;
            const bf16* src = A + (size_t)(ok ? gr : 0) * K + kk + ch * 8;
            uint32_t dst = as_base + st * (128 * APITCH * 2) + (row * APITCH + ch * 8) * 2;
            CP_ASYNC16(dst, src, ok);
        }
#pragma unroll
        for (int i = 0; i < 2; i++) {
            int idx = tid + i * 256;
            int row = idx >> 4, ch = idx & 15;
            const bf16* src = B + (size_t)(kk + row) * Nc + blockCol + ch * 8;
            uint32_t dst = bs_base + st * (32 * BPITCH * 2) + (row * BPITCH + ch * 8) * 2;
            CP_ASYNC16(dst, src, 16);
        }
    };

    float c[2][8][4];
#pragma unroll
    for (int mt = 0; mt < 2; mt++)
#pragma unroll
        for (int nt = 0; nt < 8; nt++)
#pragma unroll
            for (int q = 0; q < 4; q++) c[mt][nt][q] = 0.f;

    prefetch(0);
    CP_COMMIT();

#pragma unroll 1
    for (int it = 0; it < nIter; it++) {
        if (it + 1 < nIter) {
            prefetch(it + 1);
            CP_COMMIT();
            CP_WAIT1();
        } else {
            CP_WAIT0();
        }
        __syncthreads();

        const int st = it & 1;
        const bf16* as = As[st];
        const bf16* bs = Bs[st];
#pragma unroll
        for (int ks = 0; ks < 2; ks++) {
            uint32_t af[2][4], bfr[4][4];
#pragma unroll
            for (int mt = 0; mt < 2; mt++) {
                int row = wm * 32 + mt * 16 + (lane & 15);
                int col = ks * 16 + (lane >> 4) * 8;
                uint32_t addr = (uint32_t)__cvta_generic_to_shared(&as[row * APITCH + col]);
                asm volatile(
                    "ldmatrix.sync.aligned.m8n8.x4.shared.b16 {%0,%1,%2,%3}, [%4];"
                    : "=r"(af[mt][0]), "=r"(af[mt][1]), "=r"(af[mt][2]), "=r"(af[mt][3])
                    : "r"(addr));
            }
#pragma unroll
            for (int bt = 0; bt < 4; bt++) {
                int row = ks * 16 + (lane & 15);
                int col = wn * 64 + bt * 16 + (lane >> 4) * 8;
                uint32_t addr = (uint32_t)__cvta_generic_to_shared(&bs[row * BPITCH + col]);
                asm volatile(
                    "ldmatrix.sync.aligned.m8n8.x4.trans.shared.b16 {%0,%1,%2,%3}, [%4];"
                    : "=r"(bfr[bt][0]), "=r"(bfr[bt][1]), "=r"(bfr[bt][2]), "=r"(bfr[bt][3])
                    : "r"(addr));
            }
#pragma unroll
            for (int mt = 0; mt < 2; mt++)
#pragma unroll
                for (int nt = 0; nt < 8; nt++) {
                    const uint32_t b0 = bfr[nt >> 1][(nt & 1) * 2];
                    const uint32_t b1 = bfr[nt >> 1][(nt & 1) * 2 + 1];
                    asm volatile(
                        "mma.sync.aligned.m16n8k16.row.col.f32.bf16.bf16.f32 "
                        "{%0,%1,%2,%3}, {%4,%5,%6,%7}, {%8,%9}, {%0,%1,%2,%3};"
                        : "+f"(c[mt][nt][0]), "+f"(c[mt][nt][1]),
                          "+f"(c[mt][nt][2]), "+f"(c[mt][nt][3])
                        : "r"(af[mt][0]), "r"(af[mt][1]), "r"(af[mt][2]), "r"(af[mt][3]),
                          "r"(b0), "r"(b1));
                }
        }
        __syncthreads();
    }

    // epilogue: fp16 stores
#pragma unroll
    for (int mt = 0; mt < 2; mt++) {
#pragma unroll
        for (int half_ = 0; half_ < 2; half_++) {
            int row = blockRow + wm * 32 + mt * 16 + half_ * 8 + (lane >> 2);
            if (row >= M) continue;
#pragma unroll
            for (int nt = 0; nt < 8; nt++) {
                int gcol = blockCol + wn * 64 + nt * 8 + (lane & 3) * 2;
                __half2 hv = __floats2half2_rn(c[mt][nt][half_ * 2 + 0],
                                               c[mt][nt][half_ * 2 + 1]);
                __half* Cp = (gcol < 256) ? C0 : C1;
                int cc = gcol & 255;
                *(__half2*)&Cp[(size_t)row * 256 + cc] = hv;
            }
        }
    }
}

// ---------------- launch ----------------
extern "C" void kernel_launch(void* const* d_in, const int* in_sizes, int n_in,
                              void* d_out, int out_size) {
    (void)in_sizes; (void)n_in; (void)out_size;
    const float* x   = (const float*)d_in[0];
    const float* x1  = (const float*)d_in[1];
    const int*   ei  = (const int*)d_in[2];
    const int*   src = ei;
    const int*   dst = ei + EE;
    const float* gw0 = (const float*)d_in[3];
    const float* gb0 = (const float*)d_in[4];
    const float* gw1 = (const float*)d_in[5];
    const float* gb1 = (const float*)d_in[6];
    const float* wl0 = (const float*)d_in[7];
    const float* bl0 = (const float*)d_in[8];
    const float* wr0 = (const float*)d_in[9];
    const float* wl1 = (const float*)d_in[10];
    const float* bl1 = (const float*)d_in[11];
    const float* wr1 = (const float*)d_in[12];
    const float* lw  = (const float*)d_in[13];
    const float* lb  = (const float*)d_in[14];
    float* out = (float*)d_out;

    __half *p_Pl, *p_Pr;
    cudaGetSymbolAddress((void**)&p_Pl, d_Pl);
    cudaGetSymbolAddress((void**)&p_Pr, d_Pr);

    bf16 *p_h1h, *p_h1l, *p_hch, *p_hcl, *p_h2h, *p_h2l;
    cudaGetSymbolAddress((void**)&p_h1h, d_h1h);
    cudaGetSymbolAddress((void**)&p_h1l, d_h1l);
    cudaGetSymbolAddress((void**)&p_hch, d_hch);
    cudaGetSymbolAddress((void**)&p_hcl, d_hcl);
    cudaGetSymbolAddress((void**)&p_h2h, d_h2h);
    cudaGetSymbolAddress((void**)&p_h2l, d_h2l);

    bf16 *p_gw1h, *p_gw1l, *p_w0h, *p_w0l, *p_w1h, *p_w1l;
    cudaGetSymbolAddress((void**)&p_gw1h, d_gw1h);
    cudaGetSymbolAddress((void**)&p_gw1l, d_gw1l);
    cudaGetSymbolAddress((void**)&p_w0h, d_w0h);
    cudaGetSymbolAddress((void**)&p_w0l, d_w0l);
    cudaGetSymbolAddress((void**)&p_w1h, d_w1h);
    cudaGetSymbolAddress((void**)&p_w1l, d_w1l);

    // CSR build + degrees
    k_zero_cnt<<<(NN + 255) / 256, 256>>>();
    k_count<<<(EE + 255) / 256, 256>>>(dst);
    k_scan1<<<NB_SCAN, 1024>>>();
    k_scan2<<<1, 32>>>();
    k_scan3<<<(NN + 1 + 255) / 256, 256>>>();
    k_fill<<<(EE + 255) / 256, 256>>>(src, dst);

    // weight splits (pack SAGE layers as [Wl | Wr] with pitch 512)
    k_split_w<<<(HH * HH + 255) / 256, 256>>>(gw1, p_gw1h, p_gw1l, HH * HH, HH, 0);
    k_split_w<<<(FH * HH + 255) / 256, 256>>>(wl0, p_w0h, p_w0l, FH * HH, 512, 0);
    k_split_w<<<(FH * HH + 255) / 256, 256>>>(wr0, p_w0h, p_w0l, FH * HH, 512, 256);
    k_split_w<<<(HH * HH + 255) / 256, 256>>>(wl1, p_w1h, p_w1l, HH * HH, 512, 0);
    k_split_w<<<(HH * HH + 255) / 256, 256>>>(wr1, p_w1h, p_w1l, HH * HH, 512, 256);

    // x -> hcat cols 0..63 (hi/lo)
    k_split_x<<<(NN * FF + 255) / 256, 256>>>(x);

    // GIN layer 0 (K = 1)
    k_gin0_agg<<<(NN + 255) / 256, 256>>>(x1);
    k_gin0_act<<<(NN * HH + 255) / 256, 256>>>(gw0, gb0);

    // GIN layer 1: Pl = h1 @ gw1; h1b = tanh(Pl_self + agg(Pl) + gb1) -> hcat cols 64..319
    {
        PanelArgs pa;
        pa.A[0] = p_h1h; pa.B[0] = p_gw1h;
        pa.A[1] = p_h1l; pa.B[1] = p_gw1h;
        pa.A[2] = p_h1h; pa.B[2] = p_gw1l;
        k_mma<<<dim3(HH / 128, MBLK), 256>>>(pa, HH, HH, p_Pl, nullptr, NN);
    }
    k_comb_gin<<<NN, 64>>>(p_Pl, gb1);

    // SAGE layer 0
    {
        PanelArgs pa;
        pa.A[0] = p_hch; pa.B[0] = p_w0h;
        pa.A[1] = p_hcl; pa.B[1] = p_w0h;
        pa.A[2] = p_hch; pa.B[2] = p_w0l;
        k_mma<<<dim3(512 / 128, MBLK), 256>>>(pa, FH, 512, p_Pl, p_Pr, NN);
    }
    k_comb_sage<<<NN, 64>>>(p_Pl, p_Pr, bl0, p_h2h, p_h2l);

    // SAGE layer 1 + output head
    {
        PanelArgs pa;
        pa.A[0] = p_h2h; pa.B[0] = p_w1h;
        pa.A[1] = p_h2l; pa.B[1] = p_w1h;
        pa.A[2] = p_h2h; pa.B[2] = p_w1l;
        k_mma<<<dim3(512 / 128, MBLK), 256>>>(pa, HH, 512, p_Pl, p_Pr, NN);
    }
    k_comb_sage_out<<<NN, 64>>>(p_Pl, p_Pr, bl1, lw, lb, out);
}

// round 7
// speedup vs baseline: 2.6203x; 1.3267x over previous
#include <cuda_runtime.h>
#include <cuda_fp16.h>
#include <math.h>
#include <stdint.h>

// Problem constants
static const int NN = 50000;
static const int FF = 64;
static const int HH = 256;
static const int EE = 1600000;
static const int FH = 320;                     // FF + HH
static const int NB_SCAN = (NN + 1023) / 1024; // 49
static const int MBLK = (NN + 127) / 128;      // 391
static const int NCB = (NN + 7) / 8;           // 6250 combine blocks

// ---------------- scratch (__device__ globals; allocation-free) ----------------
__device__ int   d_cnt[NN];
__device__ int   d_rowptr[NN + 1];
__device__ int   d_fill[NN];
__device__ int   d_col[EE];
__device__ int   d_bsum[64];
__device__ float d_deg[NN];
__device__ float d_g1[NN];
// fp16 activation buffers (GEMM A operands)
__device__ __align__(16) __half d_h1[NN * HH];    // tanh(gin0)
__device__ __align__(16) __half d_hcat[NN * FH];  // [x | h1b]
__device__ __align__(16) __half d_h2[NN * HH];    // relu(sage0)
// fp16 projection outputs
__device__ __align__(16) __half d_Pl[NN * HH];
__device__ __align__(16) __half d_Pr[NN * HH];
// fp16 hi/lo weights
__device__ __align__(16) __half d_gw1h[HH * HH];     // [256,256]
__device__ __align__(16) __half d_gw1l[HH * HH];
__device__ __align__(16) __half d_w0h[FH * 2 * HH];  // [320,512] = [Wl0|Wr0]
__device__ __align__(16) __half d_w0l[FH * 2 * HH];
__device__ __align__(16) __half d_w1h[HH * 2 * HH];  // [256,512] = [Wl1|Wr1]
__device__ __align__(16) __half d_w1l[HH * 2 * HH];

// ---------------- CSR build ----------------
__global__ void k_zero_cnt() {
    int i = blockIdx.x * blockDim.x + threadIdx.x;
    if (i < NN) d_cnt[i] = 0;
}

__global__ void k_count(const int* __restrict__ dst) {
    int e = blockIdx.x * blockDim.x + threadIdx.x;
    if (e < EE) atomicAdd(&d_cnt[dst[e]], 1);
}

__global__ void k_scan1() {
    __shared__ int sh[1024];
    int tid = threadIdx.x;
    int i = blockIdx.x * 1024 + tid;
    int v = (i < NN) ? d_cnt[i] : 0;
    sh[tid] = v;
    __syncthreads();
#pragma unroll
    for (int off = 1; off < 1024; off <<= 1) {
        int t = (tid >= off) ? sh[tid - off] : 0;
        __syncthreads();
        sh[tid] += t;
        __syncthreads();
    }
    if (i < NN) d_rowptr[i] = sh[tid] - v; // exclusive
    if (tid == 1023) d_bsum[blockIdx.x] = sh[1023];
}

__global__ void k_scan2() {
    if (threadIdx.x == 0 && blockIdx.x == 0) {
        int run = 0;
        for (int b = 0; b < NB_SCAN; b++) {
            int t = d_bsum[b];
            d_bsum[b] = run;
            run += t;
        }
    }
}

__global__ void k_scan3() {
    int i = blockIdx.x * blockDim.x + threadIdx.x;
    if (i < NN) {
        int r = d_rowptr[i] + d_bsum[i >> 10];
        d_rowptr[i] = r;
        d_fill[i] = r;
        float c = (float)d_cnt[i];
        d_deg[i] = fmaxf(c, 1.0f);
    } else if (i == NN) {
        d_rowptr[NN] = EE;
    }
}

__global__ void k_fill(const int* __restrict__ src, const int* __restrict__ dst) {
    int e = blockIdx.x * blockDim.x + threadIdx.x;
    if (e < EE) {
        int pos = atomicAdd(&d_fill[dst[e]], 1);
        d_col[pos] = src[e];
    }
}

// ---------------- split helpers ----------------
__device__ __forceinline__ void split2h(float v, __half& h, __half& l) {
    h = __float2half_rn(v);
    l = __float2half_rn(v - __half2float(h));
}

// W [K, 256] row-major -> Wh/Wl [K, pitch] fp16 hi/lo with column offset
__global__ void k_split_w(const float* __restrict__ W, __half* __restrict__ Wh,
                          __half* __restrict__ Wl, int n, int pitch, int coloff) {
    int i = blockIdx.x * blockDim.x + threadIdx.x;
    if (i >= n) return;
    int k = i >> 8;
    int c = i & 255;
    __half h, l;
    split2h(W[i], h, l);
    size_t o = (size_t)k * pitch + coloff + c;
    Wh[o] = h; Wl[o] = l;
}

// x [N,64] fp32 -> hcat fp16 cols 0..63 (pitch 320)
__global__ void k_split_x(const float* __restrict__ x) {
    int i = blockIdx.x * blockDim.x + threadIdx.x;
    if (i >= NN * FF) return;
    int r = i >> 6;
    int c = i & 63;
    d_hcat[(size_t)r * FH + c] = __float2half_rn(x[i]);
}

// ---------------- GIN0 (K = 1) ----------------
__global__ void k_gin0_agg(const float* __restrict__ x1) {
    int i = blockIdx.x * blockDim.x + threadIdx.x;
    if (i >= NN) return;
    int beg = d_rowptr[i], end = d_rowptr[i + 1];
    float s = x1[i]; // self (eps = 0)
    for (int j = beg; j < end; j++) s += x1[d_col[j]];
    d_g1[i] = s;
}

__global__ void k_gin0_act(const float* __restrict__ w0, const float* __restrict__ b0) {
    int idx = blockIdx.x * blockDim.x + threadIdx.x;
    if (idx >= NN * HH) return;
    int i = idx >> 8;
    int c = idx & 255;
    d_h1[idx] = __float2half_rn(tanhf(d_g1[i] * w0[c] + b0[c]));
}

// ---------------- fused gather + combine (warp per node, uint4 loads) ----------------
// Node row = 256 fp16 = 32 x uint4; lane handles halves [8*lane, 8*lane+8).

__device__ __forceinline__ void acc_u4(float* a, uint4 u) {
    float2 f;
    f = __half22float2(*(__half2*)&u.x); a[0] += f.x; a[1] += f.y;
    f = __half22float2(*(__half2*)&u.y); a[2] += f.x; a[3] += f.y;
    f = __half22float2(*(__half2*)&u.z); a[4] += f.x; a[5] += f.y;
    f = __half22float2(*(__half2*)&u.w); a[6] += f.x; a[7] += f.y;
}

__device__ __forceinline__ void gather_sum(float* a, const uint4* __restrict__ P4,
                                           int beg, int end, int lane) {
    int j = beg;
    for (; j + 1 < end; j += 2) {
        int s0 = d_col[j], s1 = d_col[j + 1];
        uint4 u0 = P4[(size_t)s0 * 32 + lane];
        uint4 u1 = P4[(size_t)s1 * 32 + lane];
        acc_u4(a, u0); acc_u4(a, u1);
    }
    if (j < end) acc_u4(a, P4[(size_t)d_col[j] * 32 + lane]);
}

__device__ __forceinline__ uint4 pack8h(const float* a) {
    uint4 r;
    *(__half2*)&r.x = __floats2half2_rn(a[0], a[1]);
    *(__half2*)&r.y = __floats2half2_rn(a[2], a[3]);
    *(__half2*)&r.z = __floats2half2_rn(a[4], a[5]);
    *(__half2*)&r.w = __floats2half2_rn(a[6], a[7]);
    return r;
}

// GIN1: hcat[64..319] = tanh(P[node] + sum_nbr P[nbr] + b)
__global__ void k_comb_gin(const __half* __restrict__ P,
                           const float* __restrict__ bias) {
    int node = blockIdx.x * 8 + (threadIdx.x >> 5);
    if (node >= NN) return;
    int lane = threadIdx.x & 31;
    const uint4* P4 = (const uint4*)P;
    float a[8] = {0, 0, 0, 0, 0, 0, 0, 0};
    gather_sum(a, P4, d_rowptr[node], d_rowptr[node + 1], lane);
    acc_u4(a, P4[(size_t)node * 32 + lane]); // self
    const float4* b4 = (const float4*)&bias[lane * 8];
    float4 b0 = b4[0], b1 = b4[1];
    a[0] = tanhf(a[0] + b0.x); a[1] = tanhf(a[1] + b0.y);
    a[2] = tanhf(a[2] + b0.z); a[3] = tanhf(a[3] + b0.w);
    a[4] = tanhf(a[4] + b1.x); a[5] = tanhf(a[5] + b1.y);
    a[6] = tanhf(a[6] + b1.z); a[7] = tanhf(a[7] + b1.w);
    *(uint4*)&d_hcat[(size_t)node * FH + 64 + lane * 8] = pack8h(a);
}

// SAGE: out = relu(sum_nbr Pl[nbr]/deg + b + Pr[node])
__global__ void k_comb_sage(const __half* __restrict__ Pl,
                            const __half* __restrict__ Pr,
                            const float* __restrict__ bias,
                            __half* __restrict__ outp) {
    int node = blockIdx.x * 8 + (threadIdx.x >> 5);
    if (node >= NN) return;
    int lane = threadIdx.x & 31;
    const uint4* Pl4 = (const uint4*)Pl;
    const uint4* Pr4 = (const uint4*)Pr;
    float a[8] = {0, 0, 0, 0, 0, 0, 0, 0};
    gather_sum(a, Pl4, d_rowptr[node], d_rowptr[node + 1], lane);
    float inv = 1.0f / d_deg[node];
    float r[8] = {0, 0, 0, 0, 0, 0, 0, 0};
    acc_u4(r, Pr4[(size_t)node * 32 + lane]);
    const float4* b4 = (const float4*)&bias[lane * 8];
    float4 b0 = b4[0], b1 = b4[1];
    a[0] = fmaxf(a[0] * inv + b0.x + r[0], 0.f);
    a[1] = fmaxf(a[1] * inv + b0.y + r[1], 0.f);
    a[2] = fmaxf(a[2] * inv + b0.z + r[2], 0.f);
    a[3] = fmaxf(a[3] * inv + b0.w + r[3], 0.f);
    a[4] = fmaxf(a[4] * inv + b1.x + r[4], 0.f);
    a[5] = fmaxf(a[5] * inv + b1.y + r[5], 0.f);
    a[6] = fmaxf(a[6] * inv + b1.z + r[6], 0.f);
    a[7] = fmaxf(a[7] * inv + b1.w + r[7], 0.f);
    *(uint4*)&outp[(size_t)node * HH + lane * 8] = pack8h(a);
}

// SAGE final + fused head: out[node] = relu(...) . lw + lb  (256 -> 2)
__global__ void k_comb_sage_out(const __half* __restrict__ Pl,
                                const __half* __restrict__ Pr,
                                const float* __restrict__ bias,
                                const float* __restrict__ lw,
                                const float* __restrict__ lb,
                                float* __restrict__ out) {
    int node = blockIdx.x * 8 + (threadIdx.x >> 5);
    if (node >= NN) return;
    int lane = threadIdx.x & 31;
    const uint4* Pl4 = (const uint4*)Pl;
    const uint4* Pr4 = (const uint4*)Pr;
    float a[8] = {0, 0, 0, 0, 0, 0, 0, 0};
    gather_sum(a, Pl4, d_rowptr[node], d_rowptr[node + 1], lane);
    float inv = 1.0f / d_deg[node];
    float r[8] = {0, 0, 0, 0, 0, 0, 0, 0};
    acc_u4(r, Pr4[(size_t)node * 32 + lane]);
    const float4* b4 = (const float4*)&bias[lane * 8];
    float4 b0 = b4[0], b1 = b4[1];
    a[0] = fmaxf(a[0] * inv + b0.x + r[0], 0.f);
    a[1] = fmaxf(a[1] * inv + b0.y + r[1], 0.f);
    a[2] = fmaxf(a[2] * inv + b0.z + r[2], 0.f);
    a[3] = fmaxf(a[3] * inv + b0.w + r[3], 0.f);
    a[4] = fmaxf(a[4] * inv + b1.x + r[4], 0.f);
    a[5] = fmaxf(a[5] * inv + b1.y + r[5], 0.f);
    a[6] = fmaxf(a[6] * inv + b1.z + r[6], 0.f);
    a[7] = fmaxf(a[7] * inv + b1.w + r[7], 0.f);
    int c = lane * 8;
    float p0 = 0.f, p1 = 0.f;
#pragma unroll
    for (int i = 0; i < 8; i++) {
        p0 += a[i] * lw[(c + i) * 2 + 0];
        p1 += a[i] * lw[(c + i) * 2 + 1];
    }
#pragma unroll
    for (int o = 16; o > 0; o >>= 1) {
        p0 += __shfl_down_sync(0xFFFFFFFFu, p0, o);
        p1 += __shfl_down_sync(0xFFFFFFFFu, p1, o);
    }
    if (lane == 0) {
        out[node * 2 + 0] = p0 + lb[0];
        out[node * 2 + 1] = p1 + lb[1];
    }
}

// ---------------- fp16 tensor-core GEMM, 2 weight panels ----------------
// C[M, Nc] = A[M,K] @ (Bh[K,Nc] + Bl[K,Nc]), fp16 A exact, fp32 accum, fp16 out.
#define CP_ASYNC16(dst, src, sz) \
    asm volatile("cp.async.cg.shared.global [%0], [%1], 16, %2;" \
                 :: "r"(dst), "l"(src), "r"(sz))
#define CP_COMMIT() asm volatile("cp.async.commit_group;")
#define CP_WAIT1()  asm volatile("cp.async.wait_group 1;")
#define CP_WAIT0()  asm volatile("cp.async.wait_group 0;")

static const int APITCH = 40;   // halves per A row (32 data + 8 pad)
static const int BPITCH = 136;  // halves per B row (128 data + 8 pad)
// smem layout in halves: As 2*128*40=10240, Bh 2*32*136=8704, Bl 8704
static const int AS_ST = 128 * APITCH;   // 5120
static const int BH_OFF = 10240;
static const int BS_ST = 32 * BPITCH;    // 4352
static const int BL_OFF = 18944;
static const int SMEM_BYTES = (10240 + 8704 + 8704) * 2; // 55296

__global__ void __launch_bounds__(256, 2)
k_mma(const __half* __restrict__ A,
      const __half* __restrict__ Bh, const __half* __restrict__ Bl,
      int K, int Nc,
      __half* __restrict__ C0, __half* __restrict__ C1, int M)
{
    extern __shared__ __half sm[];
    const int tid = threadIdx.x;
    const int lane = tid & 31, warp = tid >> 5;
    const int wm = warp >> 1, wn = warp & 1;  // 4 x 2 warp grid, 32x64 per warp
    const int blockRow = blockIdx.y * 128;
    const int blockCol = blockIdx.x * 128;

    const int nIter = K >> 5;   // BK = 32

    uint32_t sm_base = (uint32_t)__cvta_generic_to_shared(sm);

    auto prefetch = [&](int it) {
        int st = it & 1;
        int kk = it << 5;
#pragma unroll
        for (int i = 0; i < 2; i++) {
            int idx = tid + i * 256;
            int row = idx >> 2, ch = idx & 3;
            int gr = blockRow + row;
            int ok = (gr < M) ? 16 : 0;
            const __half* src = A + (size_t)(ok ? gr : 0) * K + kk + ch * 8;
            uint32_t dst = sm_base + (st * AS_ST + row * APITCH + ch * 8) * 2;
            CP_ASYNC16(dst, src, ok);
        }
#pragma unroll
        for (int i = 0; i < 2; i++) {
            int idx = tid + i * 256;
            int row = idx >> 4, ch = idx & 15;
            size_t go = (size_t)(kk + row) * Nc + blockCol + ch * 8;
            uint32_t so = (row * BPITCH + ch * 8) * 2;
            CP_ASYNC16(sm_base + (BH_OFF + st * BS_ST) * 2 + so, Bh + go, 16);
            CP_ASYNC16(sm_base + (BL_OFF + st * BS_ST) * 2 + so, Bl + go, 16);
        }
    };

    float c[2][8][4];
#pragma unroll
    for (int mt = 0; mt < 2; mt++)
#pragma unroll
        for (int nt = 0; nt < 8; nt++)
#pragma unroll
            for (int q = 0; q < 4; q++) c[mt][nt][q] = 0.f;

    prefetch(0);
    CP_COMMIT();

#pragma unroll 1
    for (int it = 0; it < nIter; it++) {
        if (it + 1 < nIter) {
            prefetch(it + 1);
            CP_COMMIT();
            CP_WAIT1();
        } else {
            CP_WAIT0();
        }
        __syncthreads();

        const int st = it & 1;
        const __half* as = sm + st * AS_ST;
        const __half* bhs = sm + BH_OFF + st * BS_ST;
        const __half* bls = sm + BL_OFF + st * BS_ST;
#pragma unroll
        for (int ks = 0; ks < 2; ks++) {
            uint32_t af[2][4];
#pragma unroll
            for (int mt = 0; mt < 2; mt++) {
                int row = wm * 32 + mt * 16 + (lane & 15);
                int col = ks * 16 + (lane >> 4) * 8;
                uint32_t addr = (uint32_t)__cvta_generic_to_shared(&as[row * APITCH + col]);
                asm volatile(
                    "ldmatrix.sync.aligned.m8n8.x4.shared.b16 {%0,%1,%2,%3}, [%4];"
                    : "=r"(af[mt][0]), "=r"(af[mt][1]), "=r"(af[mt][2]), "=r"(af[mt][3])
                    : "r"(addr));
            }
#pragma unroll
            for (int pnl = 0; pnl < 2; pnl++) {
                const __half* bs = pnl ? bls : bhs;
                uint32_t bfr[4][4];
#pragma unroll
                for (int bt = 0; bt < 4; bt++) {
                    int row = ks * 16 + (lane & 15);
                    int col = wn * 64 + bt * 16 + (lane >> 4) * 8;
                    uint32_t addr = (uint32_t)__cvta_generic_to_shared(&bs[row * BPITCH + col]);
                    asm volatile(
                        "ldmatrix.sync.aligned.m8n8.x4.trans.shared.b16 {%0,%1,%2,%3}, [%4];"
                        : "=r"(bfr[bt][0]), "=r"(bfr[bt][1]), "=r"(bfr[bt][2]), "=r"(bfr[bt][3])
                        : "r"(addr));
                }
#pragma unroll
                for (int mt = 0; mt < 2; mt++)
#pragma unroll
                    for (int nt = 0; nt < 8; nt++) {
                        const uint32_t b0 = bfr[nt >> 1][(nt & 1) * 2];
                        const uint32_t b1 = bfr[nt >> 1][(nt & 1) * 2 + 1];
                        asm volatile(
                            "mma.sync.aligned.m16n8k16.row.col.f32.f16.f16.f32 "
                            "{%0,%1,%2,%3}, {%4,%5,%6,%7}, {%8,%9}, {%0,%1,%2,%3};"
                            : "+f"(c[mt][nt][0]), "+f"(c[mt][nt][1]),
                              "+f"(c[mt][nt][2]), "+f"(c[mt][nt][3])
                            : "r"(af[mt][0]), "r"(af[mt][1]), "r"(af[mt][2]), "r"(af[mt][3]),
                              "r"(b0), "r"(b1));
                    }
            }
        }
        __syncthreads();
    }

    // epilogue: fp16 stores
#pragma unroll
    for (int mt = 0; mt < 2; mt++) {
#pragma unroll
        for (int half_ = 0; half_ < 2; half_++) {
            int row = blockRow + wm * 32 + mt * 16 + half_ * 8 + (lane >> 2);
            if (row >= M) continue;
#pragma unroll
            for (int nt = 0; nt < 8; nt++) {
                int gcol = blockCol + wn * 64 + nt * 8 + (lane & 3) * 2;
                __half2 hv = __floats2half2_rn(c[mt][nt][half_ * 2 + 0],
                                               c[mt][nt][half_ * 2 + 1]);
                __half* Cp = (gcol < 256) ? C0 : C1;
                int cc = gcol & 255;
                *(__half2*)&Cp[(size_t)row * 256 + cc] = hv;
            }
        }
    }
}

// ---------------- launch ----------------
extern "C" void kernel_launch(void* const* d_in, const int* in_sizes, int n_in,
                              void* d_out, int out_size) {
    (void)in_sizes; (void)n_in; (void)out_size;
    const float* x   = (const float*)d_in[0];
    const float* x1  = (const float*)d_in[1];
    const int*   ei  = (const int*)d_in[2];
    const int*   src = ei;
    const int*   dst = ei + EE;
    const float* gw0 = (const float*)d_in[3];
    const float* gb0 = (const float*)d_in[4];
    const float* gw1 = (const float*)d_in[5];
    const float* gb1 = (const float*)d_in[6];
    const float* wl0 = (const float*)d_in[7];
    const float* bl0 = (const float*)d_in[8];
    const float* wr0 = (const float*)d_in[9];
    const float* wl1 = (const float*)d_in[10];
    const float* bl1 = (const float*)d_in[11];
    const float* wr1 = (const float*)d_in[12];
    const float* lw  = (const float*)d_in[13];
    const float* lb  = (const float*)d_in[14];
    float* out = (float*)d_out;

    cudaFuncSetAttribute(k_mma, cudaFuncAttributeMaxDynamicSharedMemorySize, SMEM_BYTES);

    __half *p_h1, *p_hcat, *p_h2, *p_Pl, *p_Pr;
    cudaGetSymbolAddress((void**)&p_h1, d_h1);
    cudaGetSymbolAddress((void**)&p_hcat, d_hcat);
    cudaGetSymbolAddress((void**)&p_h2, d_h2);
    cudaGetSymbolAddress((void**)&p_Pl, d_Pl);
    cudaGetSymbolAddress((void**)&p_Pr, d_Pr);

    __half *p_gw1h, *p_gw1l, *p_w0h, *p_w0l, *p_w1h, *p_w1l;
    cudaGetSymbolAddress((void**)&p_gw1h, d_gw1h);
    cudaGetSymbolAddress((void**)&p_gw1l, d_gw1l);
    cudaGetSymbolAddress((void**)&p_w0h, d_w0h);
    cudaGetSymbolAddress((void**)&p_w0l, d_w0l);
    cudaGetSymbolAddress((void**)&p_w1h, d_w1h);
    cudaGetSymbolAddress((void**)&p_w1l, d_w1l);

    // CSR build + degrees
    k_zero_cnt<<<(NN + 255) / 256, 256>>>();
    k_count<<<(EE + 255) / 256, 256>>>(dst);
    k_scan1<<<NB_SCAN, 1024>>>();
    k_scan2<<<1, 32>>>();
    k_scan3<<<(NN + 1 + 255) / 256, 256>>>();
    k_fill<<<(EE + 255) / 256, 256>>>(src, dst);

    // weight splits (pack SAGE layers as [Wl | Wr] with pitch 512)
    k_split_w<<<(HH * HH + 255) / 256, 256>>>(gw1, p_gw1h, p_gw1l, HH * HH, HH, 0);
    k_split_w<<<(FH * HH + 255) / 256, 256>>>(wl0, p_w0h, p_w0l, FH * HH, 512, 0);
    k_split_w<<<(FH * HH + 255) / 256, 256>>>(wr0, p_w0h, p_w0l, FH * HH, 512, 256);
    k_split_w<<<(HH * HH + 255) / 256, 256>>>(wl1, p_w1h, p_w1l, HH * HH, 512, 0);
    k_split_w<<<(HH * HH + 255) / 256, 256>>>(wr1, p_w1h, p_w1l, HH * HH, 512, 256);

    // x -> hcat cols 0..63
    k_split_x<<<(NN * FF + 255) / 256, 256>>>(x);

    // GIN layer 0 (K = 1)
    k_gin0_agg<<<(NN + 255) / 256, 256>>>(x1);
    k_gin0_act<<<(NN * HH + 255) / 256, 256>>>(gw0, gb0);

    // GIN layer 1: Pl = h1 @ gw1; hcat[64..] = tanh(Pl_self + agg(Pl) + gb1)
    k_mma<<<dim3(2, MBLK), 256, SMEM_BYTES>>>(p_h1, p_gw1h, p_gw1l, HH, HH,
                                              p_Pl, nullptr, NN);
    k_comb_gin<<<NCB, 256>>>(p_Pl, gb1);

    // SAGE layer 0
    k_mma<<<dim3(4, MBLK), 256, SMEM_BYTES>>>(p_hcat, p_w0h, p_w0l, FH, 512,
                                              p_Pl, p_Pr, NN);
    k_comb_sage<<<NCB, 256>>>(p_Pl, p_Pr, bl0, p_h2);

    // SAGE layer 1 + output head
    k_mma<<<dim3(4, MBLK), 256, SMEM_BYTES>>>(p_h2, p_w1h, p_w1l, HH, 512,
                                              p_Pl, p_Pr, NN);
    k_comb_sage_out<<<NCB, 256>>>(p_Pl, p_Pr, bl1, lw, lb, out);
}

// round 8
// speedup vs baseline: 2.6452x; 1.0095x over previous
#include <cuda_runtime.h>
#include <cuda_fp16.h>
#include <math.h>
#include <stdint.h>

// Problem constants
static const int NN = 50000;
static const int FF = 64;
static const int HH = 256;
static const int EE = 1600000;
static const int FH = 320;                     // FF + HH
static const int NB_SCAN = (NN + 1023) / 1024; // 49
static const int MBLK = (NN + 127) / 128;      // 391
static const int NCB = (NN + 7) / 8;           // 6250 combine blocks

// ---------------- scratch (__device__ globals; allocation-free) ----------------
__device__ int   d_cnt[NN];
__device__ int   d_rowptr[NN + 1];
__device__ int   d_fill[NN];
__device__ int   d_col[EE];
__device__ int   d_bsum[64];
__device__ float d_deg[NN];
__device__ float d_g1[NN];
// fp16 activation buffers (GEMM A operands)
__device__ __align__(16) __half d_h1[NN * HH];    // tanh(gin0)
__device__ __align__(16) __half d_hcat[NN * FH];  // [x | h1b]
__device__ __align__(16) __half d_h2[NN * HH];    // relu(sage0)
// fp16 projection outputs
__device__ __align__(16) __half d_Pl[NN * HH];
__device__ __align__(16) __half d_Pr[NN * HH];
// fp16 hi/lo weights
__device__ __align__(16) __half d_gw1h[HH * HH];     // [256,256]
__device__ __align__(16) __half d_gw1l[HH * HH];
__device__ __align__(16) __half d_w0h[FH * 2 * HH];  // [320,512] = [Wl0|Wr0]
__device__ __align__(16) __half d_w0l[FH * 2 * HH];
__device__ __align__(16) __half d_w1h[HH * 2 * HH];  // [256,512] = [Wl1|Wr1]
__device__ __align__(16) __half d_w1l[HH * 2 * HH];

// ---------------- CSR build ----------------
__global__ void k_count(const int* __restrict__ dst) {
    int e = blockIdx.x * blockDim.x + threadIdx.x;
    if (e < EE) atomicAdd(&d_cnt[dst[e]], 1);
}

__global__ void k_scan1() {
    __shared__ int sh[1024];
    int tid = threadIdx.x;
    int i = blockIdx.x * 1024 + tid;
    int v = (i < NN) ? d_cnt[i] : 0;
    sh[tid] = v;
    __syncthreads();
#pragma unroll
    for (int off = 1; off < 1024; off <<= 1) {
        int t = (tid >= off) ? sh[tid - off] : 0;
        __syncthreads();
        sh[tid] += t;
        __syncthreads();
    }
    if (i < NN) d_rowptr[i] = sh[tid] - v; // exclusive
    if (tid == 1023) d_bsum[blockIdx.x] = sh[1023];
}

__global__ void k_scan2() {
    if (threadIdx.x == 0 && blockIdx.x == 0) {
        int run = 0;
        for (int b = 0; b < NB_SCAN; b++) {
            int t = d_bsum[b];
            d_bsum[b] = run;
            run += t;
        }
    }
}

__global__ void k_scan3() {
    int i = blockIdx.x * blockDim.x + threadIdx.x;
    if (i < NN) {
        int r = d_rowptr[i] + d_bsum[i >> 10];
        d_rowptr[i] = r;
        d_fill[i] = r;
        float c = (float)d_cnt[i];
        d_deg[i] = fmaxf(c, 1.0f);
    } else if (i == NN) {
        d_rowptr[NN] = EE;
    }
}

__global__ void k_fill(const int* __restrict__ src, const int* __restrict__ dst) {
    int e = blockIdx.x * blockDim.x + threadIdx.x;
    if (e < EE) {
        int pos = atomicAdd(&d_fill[dst[e]], 1);
        d_col[pos] = src[e];
    }
}

// ---------------- split helpers ----------------
__device__ __forceinline__ void split2h(float v, __half& h, __half& l) {
    h = __float2half_rn(v);
    l = __float2half_rn(v - __half2float(h));
}

// W [K, 256] row-major -> Wh/Wl [K, pitch] fp16 hi/lo with column offset
__global__ void k_split_w(const float* __restrict__ W, __half* __restrict__ Wh,
                          __half* __restrict__ Wl, int n, int pitch, int coloff) {
    int i = blockIdx.x * blockDim.x + threadIdx.x;
    if (i >= n) return;
    int k = i >> 8;
    int c = i & 255;
    __half h, l;
    split2h(W[i], h, l);
    size_t o = (size_t)k * pitch + coloff + c;
    Wh[o] = h; Wl[o] = l;
}

// x [N,64] fp32 -> hcat fp16 cols 0..63 (pitch 320)
__global__ void k_split_x(const float* __restrict__ x) {
    int i = blockIdx.x * blockDim.x + threadIdx.x;
    if (i >= NN * FF) return;
    int r = i >> 6;
    int c = i & 63;
    d_hcat[(size_t)r * FH + c] = __float2half_rn(x[i]);
}

// ---------------- GIN0 (K = 1), CSR-free scatter version ----------------
__global__ void k_g1_scatter(const int* __restrict__ src, const int* __restrict__ dst,
                             const float* __restrict__ x1) {
    int e = blockIdx.x * blockDim.x + threadIdx.x;
    if (e < EE) atomicAdd(&d_g1[dst[e]], x1[src[e]]);
}

__global__ void k_gin0_act(const float* __restrict__ x1,
                           const float* __restrict__ w0, const float* __restrict__ b0) {
    int idx = blockIdx.x * blockDim.x + threadIdx.x;
    if (idx >= NN * HH) return;
    int i = idx >> 8;
    int c = idx & 255;
    float g = d_g1[i] + x1[i]; // self term folded in
    d_h1[idx] = __float2half_rn(tanhf(g * w0[c] + b0[c]));
}

// ---------------- fused gather + combine (warp per node, uint4 loads) ----------------
// Node row = 256 fp16 = 32 x uint4; lane handles halves [8*lane, 8*lane+8).

__device__ __forceinline__ void acc_u4(float* a, uint4 u) {
    float2 f;
    f = __half22float2(*(__half2*)&u.x); a[0] += f.x; a[1] += f.y;
    f = __half22float2(*(__half2*)&u.y); a[2] += f.x; a[3] += f.y;
    f = __half22float2(*(__half2*)&u.z); a[4] += f.x; a[5] += f.y;
    f = __half22float2(*(__half2*)&u.w); a[6] += f.x; a[7] += f.y;
}

__device__ __forceinline__ void gather_sum(float* a, const uint4* __restrict__ P4,
                                           int beg, int end, int lane) {
    int j = beg;
    for (; j + 1 < end; j += 2) {
        int s0 = d_col[j], s1 = d_col[j + 1];
        uint4 u0 = P4[(size_t)s0 * 32 + lane];
        uint4 u1 = P4[(size_t)s1 * 32 + lane];
        acc_u4(a, u0); acc_u4(a, u1);
    }
    if (j < end) acc_u4(a, P4[(size_t)d_col[j] * 32 + lane]);
}

__device__ __forceinline__ uint4 pack8h(const float* a) {
    uint4 r;
    *(__half2*)&r.x = __floats2half2_rn(a[0], a[1]);
    *(__half2*)&r.y = __floats2half2_rn(a[2], a[3]);
    *(__half2*)&r.z = __floats2half2_rn(a[4], a[5]);
    *(__half2*)&r.w = __floats2half2_rn(a[6], a[7]);
    return r;
}

// GIN1: hcat[64..319] = tanh(P[node] + sum_nbr P[nbr] + b)
__global__ void k_comb_gin(const __half* __restrict__ P,
                           const float* __restrict__ bias) {
    int node = blockIdx.x * 8 + (threadIdx.x >> 5);
    if (node >= NN) return;
    int lane = threadIdx.x & 31;
    const uint4* P4 = (const uint4*)P;
    float a[8] = {0, 0, 0, 0, 0, 0, 0, 0};
    gather_sum(a, P4, d_rowptr[node], d_rowptr[node + 1], lane);
    acc_u4(a, P4[(size_t)node * 32 + lane]); // self
    const float4* b4 = (const float4*)&bias[lane * 8];
    float4 b0 = b4[0], b1 = b4[1];
    a[0] = tanhf(a[0] + b0.x); a[1] = tanhf(a[1] + b0.y);
    a[2] = tanhf(a[2] + b0.z); a[3] = tanhf(a[3] + b0.w);
    a[4] = tanhf(a[4] + b1.x); a[5] = tanhf(a[5] + b1.y);
    a[6] = tanhf(a[6] + b1.z); a[7] = tanhf(a[7] + b1.w);
    *(uint4*)&d_hcat[(size_t)node * FH + 64 + lane * 8] = pack8h(a);
}

// SAGE: out = relu(sum_nbr Pl[nbr]/deg + b + Pr[node])
__global__ void k_comb_sage(const __half* __restrict__ Pl,
                            const __half* __restrict__ Pr,
                            const float* __restrict__ bias,
                            __half* __restrict__ outp) {
    int node = blockIdx.x * 8 + (threadIdx.x >> 5);
    if (node >= NN) return;
    int lane = threadIdx.x & 31;
    const uint4* Pl4 = (const uint4*)Pl;
    const uint4* Pr4 = (const uint4*)Pr;
    float a[8] = {0, 0, 0, 0, 0, 0, 0, 0};
    gather_sum(a, Pl4, d_rowptr[node], d_rowptr[node + 1], lane);
    float inv = 1.0f / d_deg[node];
    float r[8] = {0, 0, 0, 0, 0, 0, 0, 0};
    acc_u4(r, Pr4[(size_t)node * 32 + lane]);
    const float4* b4 = (const float4*)&bias[lane * 8];
    float4 b0 = b4[0], b1 = b4[1];
    a[0] = fmaxf(a[0] * inv + b0.x + r[0], 0.f);
    a[1] = fmaxf(a[1] * inv + b0.y + r[1], 0.f);
    a[2] = fmaxf(a[2] * inv + b0.z + r[2], 0.f);
    a[3] = fmaxf(a[3] * inv + b0.w + r[3], 0.f);
    a[4] = fmaxf(a[4] * inv + b1.x + r[4], 0.f);
    a[5] = fmaxf(a[5] * inv + b1.y + r[5], 0.f);
    a[6] = fmaxf(a[6] * inv + b1.z + r[6], 0.f);
    a[7] = fmaxf(a[7] * inv + b1.w + r[7], 0.f);
    *(uint4*)&outp[(size_t)node * HH + lane * 8] = pack8h(a);
}

// SAGE final + fused head: out[node] = relu(...) . lw + lb  (256 -> 2)
__global__ void k_comb_sage_out(const __half* __restrict__ Pl,
                                const __half* __restrict__ Pr,
                                const float* __restrict__ bias,
                                const float* __restrict__ lw,
                                const float* __restrict__ lb,
                                float* __restrict__ out) {
    int node = blockIdx.x * 8 + (threadIdx.x >> 5);
    if (node >= NN) return;
    int lane = threadIdx.x & 31;
    const uint4* Pl4 = (const uint4*)Pl;
    const uint4* Pr4 = (const uint4*)Pr;
    float a[8] = {0, 0, 0, 0, 0, 0, 0, 0};
    gather_sum(a, Pl4, d_rowptr[node], d_rowptr[node + 1], lane);
    float inv = 1.0f / d_deg[node];
    float r[8] = {0, 0, 0, 0, 0, 0, 0, 0};
    acc_u4(r, Pr4[(size_t)node * 32 + lane]);
    const float4* b4 = (const float4*)&bias[lane * 8];
    float4 b0 = b4[0], b1 = b4[1];
    a[0] = fmaxf(a[0] * inv + b0.x + r[0], 0.f);
    a[1] = fmaxf(a[1] * inv + b0.y + r[1], 0.f);
    a[2] = fmaxf(a[2] * inv + b0.z + r[2], 0.f);
    a[3] = fmaxf(a[3] * inv + b0.w + r[3], 0.f);
    a[4] = fmaxf(a[4] * inv + b1.x + r[4], 0.f);
    a[5] = fmaxf(a[5] * inv + b1.y + r[5], 0.f);
    a[6] = fmaxf(a[6] * inv + b1.z + r[6], 0.f);
    a[7] = fmaxf(a[7] * inv + b1.w + r[7], 0.f);
    int c = lane * 8;
    float p0 = 0.f, p1 = 0.f;
#pragma unroll
    for (int i = 0; i < 8; i++) {
        p0 += a[i] * lw[(c + i) * 2 + 0];
        p1 += a[i] * lw[(c + i) * 2 + 1];
    }
#pragma unroll
    for (int o = 16; o > 0; o >>= 1) {
        p0 += __shfl_down_sync(0xFFFFFFFFu, p0, o);
        p1 += __shfl_down_sync(0xFFFFFFFFu, p1, o);
    }
    if (lane == 0) {
        out[node * 2 + 0] = p0 + lb[0];
        out[node * 2 + 1] = p1 + lb[1];
    }
}

// ---------------- fp16 tensor-core GEMM, 2 weight panels ----------------
#define CP_ASYNC16(dst, src, sz) \
    asm volatile("cp.async.cg.shared.global [%0], [%1], 16, %2;" \
                 :: "r"(dst), "l"(src), "r"(sz))
#define CP_COMMIT() asm volatile("cp.async.commit_group;")
#define CP_WAIT1()  asm volatile("cp.async.wait_group 1;")
#define CP_WAIT0()  asm volatile("cp.async.wait_group 0;")

static const int APITCH = 40;   // halves per A row (32 data + 8 pad)
static const int BPITCH = 136;  // halves per B row (128 data + 8 pad)
static const int AS_ST = 128 * APITCH;   // 5120
static const int BH_OFF = 10240;
static const int BS_ST = 32 * BPITCH;    // 4352
static const int BL_OFF = 18944;
static const int SMEM_BYTES = (10240 + 8704 + 8704) * 2; // 55296

__global__ void __launch_bounds__(256, 2)
k_mma(const __half* __restrict__ A,
      const __half* __restrict__ Bh, const __half* __restrict__ Bl,
      int K, int Nc,
      __half* __restrict__ C0, __half* __restrict__ C1, int M)
{
    extern __shared__ __half sm[];
    const int tid = threadIdx.x;
    const int lane = tid & 31, warp = tid >> 5;
    const int wm = warp >> 1, wn = warp & 1;  // 4 x 2 warp grid, 32x64 per warp
    const int blockRow = blockIdx.y * 128;
    const int blockCol = blockIdx.x * 128;

    const int nIter = K >> 5;   // BK = 32

    uint32_t sm_base = (uint32_t)__cvta_generic_to_shared(sm);

    auto prefetch = [&](int it) {
        int st = it & 1;
        int kk = it << 5;
#pragma unroll
        for (int i = 0; i < 2; i++) {
            int idx = tid + i * 256;
            int row = idx >> 2, ch = idx & 3;
            int gr = blockRow + row;
            int ok = (gr < M) ? 16 : 0;
            const __half* src = A + (size_t)(ok ? gr : 0) * K + kk + ch * 8;
            uint32_t dst = sm_base + (st * AS_ST + row * APITCH + ch * 8) * 2;
            CP_ASYNC16(dst, src, ok);
        }
#pragma unroll
        for (int i = 0; i < 2; i++) {
            int idx = tid + i * 256;
            int row = idx >> 4, ch = idx & 15;
            size_t go = (size_t)(kk + row) * Nc + blockCol + ch * 8;
            uint32_t so = (row * BPITCH + ch * 8) * 2;
            CP_ASYNC16(sm_base + (BH_OFF + st * BS_ST) * 2 + so, Bh + go, 16);
            CP_ASYNC16(sm_base + (BL_OFF + st * BS_ST) * 2 + so, Bl + go, 16);
        }
    };

    float c[2][8][4];
#pragma unroll
    for (int mt = 0; mt < 2; mt++)
#pragma unroll
        for (int nt = 0; nt < 8; nt++)
#pragma unroll
            for (int q = 0; q < 4; q++) c[mt][nt][q] = 0.f;

    prefetch(0);
    CP_COMMIT();

#pragma unroll 1
    for (int it = 0; it < nIter; it++) {
        if (it + 1 < nIter) {
            prefetch(it + 1);
            CP_COMMIT();
            CP_WAIT1();
        } else {
            CP_WAIT0();
        }
        __syncthreads();

        const int st = it & 1;
        const __half* as = sm + st * AS_ST;
        const __half* bhs = sm + BH_OFF + st * BS_ST;
        const __half* bls = sm + BL_OFF + st * BS_ST;
#pragma unroll
        for (int ks = 0; ks < 2; ks++) {
            uint32_t af[2][4];
#pragma unroll
            for (int mt = 0; mt < 2; mt++) {
                int row = wm * 32 + mt * 16 + (lane & 15);
                int col = ks * 16 + (lane >> 4) * 8;
                uint32_t addr = (uint32_t)__cvta_generic_to_shared(&as[row * APITCH + col]);
                asm volatile(
                    "ldmatrix.sync.aligned.m8n8.x4.shared.b16 {%0,%1,%2,%3}, [%4];"
                    : "=r"(af[mt][0]), "=r"(af[mt][1]), "=r"(af[mt][2]), "=r"(af[mt][3])
                    : "r"(addr));
            }
#pragma unroll
            for (int pnl = 0; pnl < 2; pnl++) {
                const __half* bs = pnl ? bls : bhs;
                uint32_t bfr[4][4];
#pragma unroll
                for (int bt = 0; bt < 4; bt++) {
                    int row = ks * 16 + (lane & 15);
                    int col = wn * 64 + bt * 16 + (lane >> 4) * 8;
                    uint32_t addr = (uint32_t)__cvta_generic_to_shared(&bs[row * BPITCH + col]);
                    asm volatile(
                        "ldmatrix.sync.aligned.m8n8.x4.trans.shared.b16 {%0,%1,%2,%3}, [%4];"
                        : "=r"(bfr[bt][0]), "=r"(bfr[bt][1]), "=r"(bfr[bt][2]), "=r"(bfr[bt][3])
                        : "r"(addr));
                }
#pragma unroll
                for (int mt = 0; mt < 2; mt++)
#pragma unroll
                    for (int nt = 0; nt < 8; nt++) {
                        const uint32_t b0 = bfr[nt >> 1][(nt & 1) * 2];
                        const uint32_t b1 = bfr[nt >> 1][(nt & 1) * 2 + 1];
                        asm volatile(
                            "mma.sync.aligned.m16n8k16.row.col.f32.f16.f16.f32 "
                            "{%0,%1,%2,%3}, {%4,%5,%6,%7}, {%8,%9}, {%0,%1,%2,%3};"
                            : "+f"(c[mt][nt][0]), "+f"(c[mt][nt][1]),
                              "+f"(c[mt][nt][2]), "+f"(c[mt][nt][3])
                            : "r"(af[mt][0]), "r"(af[mt][1]), "r"(af[mt][2]), "r"(af[mt][3]),
                              "r"(b0), "r"(b1));
                    }
            }
        }
        __syncthreads();
    }

    // epilogue: fp16 stores
#pragma unroll
    for (int mt = 0; mt < 2; mt++) {
#pragma unroll
        for (int half_ = 0; half_ < 2; half_++) {
            int row = blockRow + wm * 32 + mt * 16 + half_ * 8 + (lane >> 2);
            if (row >= M) continue;
#pragma unroll
            for (int nt = 0; nt < 8; nt++) {
                int gcol = blockCol + wn * 64 + nt * 8 + (lane & 3) * 2;
                __half2 hv = __floats2half2_rn(c[mt][nt][half_ * 2 + 0],
                                               c[mt][nt][half_ * 2 + 1]);
                __half* Cp = (gcol < 256) ? C0 : C1;
                int cc = gcol & 255;
                *(__half2*)&Cp[(size_t)row * 256 + cc] = hv;
            }
        }
    }
}

// ---------------- launch ----------------
extern "C" void kernel_launch(void* const* d_in, const int* in_sizes, int n_in,
                              void* d_out, int out_size) {
    (void)in_sizes; (void)n_in; (void)out_size;
    const float* x   = (const float*)d_in[0];
    const float* x1  = (const float*)d_in[1];
    const int*   ei  = (const int*)d_in[2];
    const int*   src = ei;
    const int*   dst = ei + EE;
    const float* gw0 = (const float*)d_in[3];
    const float* gb0 = (const float*)d_in[4];
    const float* gw1 = (const float*)d_in[5];
    const float* gb1 = (const float*)d_in[6];
    const float* wl0 = (const float*)d_in[7];
    const float* bl0 = (const float*)d_in[8];
    const float* wr0 = (const float*)d_in[9];
    const float* wl1 = (const float*)d_in[10];
    const float* bl1 = (const float*)d_in[11];
    const float* wr1 = (const float*)d_in[12];
    const float* lw  = (const float*)d_in[13];
    const float* lb  = (const float*)d_in[14];
    float* out = (float*)d_out;

    cudaFuncSetAttribute(k_mma, cudaFuncAttributeMaxDynamicSharedMemorySize, SMEM_BYTES);

    __half *p_h1, *p_hcat, *p_h2, *p_Pl, *p_Pr;
    cudaGetSymbolAddress((void**)&p_h1, d_h1);
    cudaGetSymbolAddress((void**)&p_hcat, d_hcat);
    cudaGetSymbolAddress((void**)&p_h2, d_h2);
    cudaGetSymbolAddress((void**)&p_Pl, d_Pl);
    cudaGetSymbolAddress((void**)&p_Pr, d_Pr);

    __half *p_gw1h, *p_gw1l, *p_w0h, *p_w0l, *p_w1h, *p_w1l;
    cudaGetSymbolAddress((void**)&p_gw1h, d_gw1h);
    cudaGetSymbolAddress((void**)&p_gw1l, d_gw1l);
    cudaGetSymbolAddress((void**)&p_w0h, d_w0h);
    cudaGetSymbolAddress((void**)&p_w0l, d_w0l);
    cudaGetSymbolAddress((void**)&p_w1h, d_w1h);
    cudaGetSymbolAddress((void**)&p_w1l, d_w1l);

    void *p_cnt, *p_g1;
    cudaGetSymbolAddress(&p_cnt, d_cnt);
    cudaGetSymbolAddress(&p_g1, d_g1);

    // one-time aux stream + events (resource creation only; identical work per call)
    static cudaStream_t s_aux = nullptr;
    static cudaEvent_t ev_fork = nullptr, ev_join = nullptr;
    if (s_aux == nullptr) {
        cudaStreamCreateWithFlags(&s_aux, cudaStreamNonBlocking);
        cudaEventCreateWithFlags(&ev_fork, cudaEventDisableTiming);
        cudaEventCreateWithFlags(&ev_join, cudaEventDisableTiming);
    }

    // ---- fork: aux stream does splits + GIN0 + GEMM1 while main builds CSR ----
    cudaEventRecord(ev_fork, 0);
    cudaStreamWaitEvent(s_aux, ev_fork, 0);

    // aux stream chain (independent of CSR)
    k_split_w<<<(HH * HH + 255) / 256, 256, 0, s_aux>>>(gw1, p_gw1h, p_gw1l, HH * HH, HH, 0);
    k_split_w<<<(FH * HH + 255) / 256, 256, 0, s_aux>>>(wl0, p_w0h, p_w0l, FH * HH, 512, 0);
    k_split_w<<<(FH * HH + 255) / 256, 256, 0, s_aux>>>(wr0, p_w0h, p_w0l, FH * HH, 512, 256);
    k_split_w<<<(HH * HH + 255) / 256, 256, 0, s_aux>>>(wl1, p_w1h, p_w1l, HH * HH, 512, 0);
    k_split_w<<<(HH * HH + 255) / 256, 256, 0, s_aux>>>(wr1, p_w1h, p_w1l, HH * HH, 512, 256);
    k_split_x<<<(NN * FF + 255) / 256, 256, 0, s_aux>>>(x);
    cudaMemsetAsync(p_g1, 0, NN * sizeof(float), s_aux);
    k_g1_scatter<<<(EE + 255) / 256, 256, 0, s_aux>>>(src, dst, x1);
    k_gin0_act<<<(NN * HH + 255) / 256, 256, 0, s_aux>>>(x1, gw0, gb0);
    k_mma<<<dim3(2, MBLK), 256, SMEM_BYTES, s_aux>>>(p_h1, p_gw1h, p_gw1l, HH, HH,
                                                     p_Pl, nullptr, NN);
    cudaEventRecord(ev_join, s_aux);

    // main stream: CSR build + degrees
    cudaMemsetAsync(p_cnt, 0, NN * sizeof(int), 0);
    k_count<<<(EE + 255) / 256, 256>>>(dst);
    k_scan1<<<NB_SCAN, 1024>>>();
    k_scan2<<<1, 32>>>();
    k_scan3<<<(NN + 1 + 255) / 256, 256>>>();
    k_fill<<<(EE + 255) / 256, 256>>>(src, dst);

    // ---- join ----
    cudaStreamWaitEvent(0, ev_join, 0);

    // GIN layer 1 combine: hcat[64..] = tanh(Pl_self + agg(Pl) + gb1)
    k_comb_gin<<<NCB, 256>>>(p_Pl, gb1);

    // SAGE layer 0
    k_mma<<<dim3(4, MBLK), 256, SMEM_BYTES>>>(p_hcat, p_w0h, p_w0l, FH, 512,
                                              p_Pl, p_Pr, NN);
    k_comb_sage<<<NCB, 256>>>(p_Pl, p_Pr, bl0, p_h2);

    // SAGE layer 1 + output head
    k_mma<<<dim3(4, MBLK), 256, SMEM_BYTES>>>(p_h2, p_w1h, p_w1l, HH, 512,
                                              p_Pl, p_Pr, NN);
    k_comb_sage_out<<<NCB, 256>>>(p_Pl, p_Pr, bl1, lw, lb, out);
}

// round 9
// speedup vs baseline: 3.1160x; 1.1780x over previous
#include <cuda_runtime.h>
#include <cuda_fp16.h>
#include <math.h>
#include <stdint.h>

// Problem constants
static const int NN = 50000;
static const int FF = 64;
static const int HH = 256;
static const int EE = 1600000;
static const int FH = 320;                     // FF + HH
static const int NB_SCAN = (NN + 1023) / 1024; // 49
static const int MBLK = (NN + 127) / 128;      // 391
static const int NCB = (NN + 7) / 8;           // 6250 combine blocks

// ---------------- scratch (__device__ globals; allocation-free) ----------------
__device__ int   d_cnt[NN];
__device__ int   d_rowptr[NN + 1];
__device__ int   d_fill[NN];
__device__ int   d_col[EE];
__device__ int   d_bsum[64];
__device__ float d_deg[NN];
__device__ float d_g1[NN];
// fp16 activation buffers (GEMM A operands)
__device__ __align__(16) __half d_h1[NN * HH];    // tanh(gin0)
__device__ __align__(16) __half d_hcat[NN * FH];  // [x | h1b]
__device__ __align__(16) __half d_h2[NN * HH];    // relu(sage0)
// fp16 projection outputs
__device__ __align__(16) __half d_Pl[NN * HH];
__device__ __align__(16) __half d_Pr[NN * HH];
// fp16 weights
__device__ __align__(16) __half d_gw1[HH * HH];     // [256,256]
__device__ __align__(16) __half d_w0[FH * 2 * HH];  // [320,512] = [Wl0|Wr0]
__device__ __align__(16) __half d_w1[HH * 2 * HH];  // [256,512] = [Wl1|Wr1]

// ---------------- CSR build ----------------
__global__ void k_count(const int* __restrict__ dst) {
    int e = blockIdx.x * blockDim.x + threadIdx.x;
    if (e < EE) atomicAdd(&d_cnt[dst[e]], 1);
}

__global__ void k_scan1() {
    __shared__ int sh[1024];
    int tid = threadIdx.x;
    int i = blockIdx.x * 1024 + tid;
    int v = (i < NN) ? d_cnt[i] : 0;
    sh[tid] = v;
    __syncthreads();
#pragma unroll
    for (int off = 1; off < 1024; off <<= 1) {
        int t = (tid >= off) ? sh[tid - off] : 0;
        __syncthreads();
        sh[tid] += t;
        __syncthreads();
    }
    if (i < NN) d_rowptr[i] = sh[tid] - v; // exclusive
    if (tid == 1023) d_bsum[blockIdx.x] = sh[1023];
}

__global__ void k_scan2() {
    if (threadIdx.x == 0 && blockIdx.x == 0) {
        int run = 0;
        for (int b = 0; b < NB_SCAN; b++) {
            int t = d_bsum[b];
            d_bsum[b] = run;
            run += t;
        }
    }
}

__global__ void k_scan3() {
    int i = blockIdx.x * blockDim.x + threadIdx.x;
    if (i < NN) {
        int r = d_rowptr[i] + d_bsum[i >> 10];
        d_rowptr[i] = r;
        d_fill[i] = r;
        float c = (float)d_cnt[i];
        d_deg[i] = fmaxf(c, 1.0f);
    } else if (i == NN) {
        d_rowptr[NN] = EE;
    }
}

__global__ void k_fill(const int* __restrict__ src, const int* __restrict__ dst) {
    int e = blockIdx.x * blockDim.x + threadIdx.x;
    if (e < EE) {
        int pos = atomicAdd(&d_fill[dst[e]], 1);
        d_col[pos] = src[e];
    }
}

// ---------------- weight convert ----------------
// W [K, 256] fp32 -> Wd [K, pitch] fp16 with column offset (for [Wl|Wr] packing)
__global__ void k_cvt_w(const float* __restrict__ W, __half* __restrict__ Wd,
                        int n, int pitch, int coloff) {
    int i = blockIdx.x * blockDim.x + threadIdx.x;
    if (i >= n) return;
    int k = i >> 8;
    int c = i & 255;
    Wd[(size_t)k * pitch + coloff + c] = __float2half_rn(W[i]);
}

// x [N,64] fp32 -> hcat fp16 cols 0..63 (pitch 320)
__global__ void k_split_x(const float* __restrict__ x) {
    int i = blockIdx.x * blockDim.x + threadIdx.x;
    if (i >= NN * FF) return;
    int r = i >> 6;
    int c = i & 63;
    d_hcat[(size_t)r * FH + c] = __float2half_rn(x[i]);
}

// ---------------- GIN0 (K = 1), CSR-free scatter version ----------------
__global__ void k_g1_scatter(const int* __restrict__ src, const int* __restrict__ dst,
                             const float* __restrict__ x1) {
    int e = blockIdx.x * blockDim.x + threadIdx.x;
    if (e < EE) atomicAdd(&d_g1[dst[e]], x1[src[e]]);
}

__global__ void k_gin0_act(const float* __restrict__ x1,
                           const float* __restrict__ w0, const float* __restrict__ b0) {
    int idx = blockIdx.x * blockDim.x + threadIdx.x;
    if (idx >= NN * HH) return;
    int i = idx >> 8;
    int c = idx & 255;
    float g = d_g1[i] + x1[i]; // self term folded in
    d_h1[idx] = __float2half_rn(tanhf(g * w0[c] + b0[c]));
}

// ---------------- fused gather + combine (warp per node, uint4 loads) ----------------
__device__ __forceinline__ void acc_u4(float* a, uint4 u) {
    float2 f;
    f = __half22float2(*(__half2*)&u.x); a[0] += f.x; a[1] += f.y;
    f = __half22float2(*(__half2*)&u.y); a[2] += f.x; a[3] += f.y;
    f = __half22float2(*(__half2*)&u.z); a[4] += f.x; a[5] += f.y;
    f = __half22float2(*(__half2*)&u.w); a[6] += f.x; a[7] += f.y;
}

__device__ __forceinline__ void gather_sum(float* a, const uint4* __restrict__ P4,
                                           int beg, int end, int lane) {
    int j = beg;
    for (; j + 1 < end; j += 2) {
        int s0 = d_col[j], s1 = d_col[j + 1];
        uint4 u0 = P4[(size_t)s0 * 32 + lane];
        uint4 u1 = P4[(size_t)s1 * 32 + lane];
        acc_u4(a, u0); acc_u4(a, u1);
    }
    if (j < end) acc_u4(a, P4[(size_t)d_col[j] * 32 + lane]);
}

__device__ __forceinline__ uint4 pack8h(const float* a) {
    uint4 r;
    *(__half2*)&r.x = __floats2half2_rn(a[0], a[1]);
    *(__half2*)&r.y = __floats2half2_rn(a[2], a[3]);
    *(__half2*)&r.z = __floats2half2_rn(a[4], a[5]);
    *(__half2*)&r.w = __floats2half2_rn(a[6], a[7]);
    return r;
}

// GIN1: hcat[64..319] = tanh(P[node] + sum_nbr P[nbr] + b)
__global__ void k_comb_gin(const __half* __restrict__ P,
                           const float* __restrict__ bias) {
    int node = blockIdx.x * 8 + (threadIdx.x >> 5);
    if (node >= NN) return;
    int lane = threadIdx.x & 31;
    const uint4* P4 = (const uint4*)P;
    float a[8] = {0, 0, 0, 0, 0, 0, 0, 0};
    gather_sum(a, P4, d_rowptr[node], d_rowptr[node + 1], lane);
    acc_u4(a, P4[(size_t)node * 32 + lane]); // self
    const float4* b4 = (const float4*)&bias[lane * 8];
    float4 b0 = b4[0], b1 = b4[1];
    a[0] = tanhf(a[0] + b0.x); a[1] = tanhf(a[1] + b0.y);
    a[2] = tanhf(a[2] + b0.z); a[3] = tanhf(a[3] + b0.w);
    a[4] = tanhf(a[4] + b1.x); a[5] = tanhf(a[5] + b1.y);
    a[6] = tanhf(a[6] + b1.z); a[7] = tanhf(a[7] + b1.w);
    *(uint4*)&d_hcat[(size_t)node * FH + 64 + lane * 8] = pack8h(a);
}

// SAGE: out = relu(sum_nbr Pl[nbr]/deg + b + Pr[node])
__global__ void k_comb_sage(const __half* __restrict__ Pl,
                            const __half* __restrict__ Pr,
                            const float* __restrict__ bias,
                            __half* __restrict__ outp) {
    int node = blockIdx.x * 8 + (threadIdx.x >> 5);
    if (node >= NN) return;
    int lane = threadIdx.x & 31;
    const uint4* Pl4 = (const uint4*)Pl;
    const uint4* Pr4 = (const uint4*)Pr;
    float a[8] = {0, 0, 0, 0, 0, 0, 0, 0};
    gather_sum(a, Pl4, d_rowptr[node], d_rowptr[node + 1], lane);
    float inv = 1.0f / d_deg[node];
    float r[8] = {0, 0, 0, 0, 0, 0, 0, 0};
    acc_u4(r, Pr4[(size_t)node * 32 + lane]);
    const float4* b4 = (const float4*)&bias[lane * 8];
    float4 b0 = b4[0], b1 = b4[1];
    a[0] = fmaxf(a[0] * inv + b0.x + r[0], 0.f);
    a[1] = fmaxf(a[1] * inv + b0.y + r[1], 0.f);
    a[2] = fmaxf(a[2] * inv + b0.z + r[2], 0.f);
    a[3] = fmaxf(a[3] * inv + b0.w + r[3], 0.f);
    a[4] = fmaxf(a[4] * inv + b1.x + r[4], 0.f);
    a[5] = fmaxf(a[5] * inv + b1.y + r[5], 0.f);
    a[6] = fmaxf(a[6] * inv + b1.z + r[6], 0.f);
    a[7] = fmaxf(a[7] * inv + b1.w + r[7], 0.f);
    *(uint4*)&outp[(size_t)node * HH + lane * 8] = pack8h(a);
}

// SAGE final + fused head: out[node] = relu(...) . lw + lb  (256 -> 2)
__global__ void k_comb_sage_out(const __half* __restrict__ Pl,
                                const __half* __restrict__ Pr,
                                const float* __restrict__ bias,
                                const float* __restrict__ lw,
                                const float* __restrict__ lb,
                                float* __restrict__ out) {
    int node = blockIdx.x * 8 + (threadIdx.x >> 5);
    if (node >= NN) return;
    int lane = threadIdx.x & 31;
    const uint4* Pl4 = (const uint4*)Pl;
    const uint4* Pr4 = (const uint4*)Pr;
    float a[8] = {0, 0, 0, 0, 0, 0, 0, 0};
    gather_sum(a, Pl4, d_rowptr[node], d_rowptr[node + 1], lane);
    float inv = 1.0f / d_deg[node];
    float r[8] = {0, 0, 0, 0, 0, 0, 0, 0};
    acc_u4(r, Pr4[(size_t)node * 32 + lane]);
    const float4* b4 = (const float4*)&bias[lane * 8];
    float4 b0 = b4[0], b1 = b4[1];
    a[0] = fmaxf(a[0] * inv + b0.x + r[0], 0.f);
    a[1] = fmaxf(a[1] * inv + b0.y + r[1], 0.f);
    a[2] = fmaxf(a[2] * inv + b0.z + r[2], 0.f);
    a[3] = fmaxf(a[3] * inv + b0.w + r[3], 0.f);
    a[4] = fmaxf(a[4] * inv + b1.x + r[4], 0.f);
    a[5] = fmaxf(a[5] * inv + b1.y + r[5], 0.f);
    a[6] = fmaxf(a[6] * inv + b1.z + r[6], 0.f);
    a[7] = fmaxf(a[7] * inv + b1.w + r[7], 0.f);
    int c = lane * 8;
    float p0 = 0.f, p1 = 0.f;
#pragma unroll
    for (int i = 0; i < 8; i++) {
        p0 += a[i] * lw[(c + i) * 2 + 0];
        p1 += a[i] * lw[(c + i) * 2 + 1];
    }
#pragma unroll
    for (int o = 16; o > 0; o >>= 1) {
        p0 += __shfl_down_sync(0xFFFFFFFFu, p0, o);
        p1 += __shfl_down_sync(0xFFFFFFFFu, p1, o);
    }
    if (lane == 0) {
        out[node * 2 + 0] = p0 + lb[0];
        out[node * 2 + 1] = p1 + lb[1];
    }
}

// ---------------- fp16 tensor-core GEMM, single weight panel, 3-stage pipeline ----------------
#define CP_ASYNC16(dst, src, sz) \
    asm volatile("cp.async.cg.shared.global [%0], [%1], 16, %2;" \
                 :: "r"(dst), "l"(src), "r"(sz))
#define CP_COMMIT() asm volatile("cp.async.commit_group;")
#define CP_WAIT2()  asm volatile("cp.async.wait_group 2;")
#define CP_WAIT1()  asm volatile("cp.async.wait_group 1;")
#define CP_WAIT0()  asm volatile("cp.async.wait_group 0;")

static const int APITCH = 40;   // halves per A row (32 data + 8 pad)
static const int BPITCH = 136;  // halves per B row (128 data + 8 pad)
static const int AS_ST = 128 * APITCH;   // 5120 halves per A stage
static const int BS_ST = 32 * BPITCH;    // 4352 halves per B stage
static const int B_OFF = 3 * AS_ST;      // 15360
static const int SMEM_BYTES = (3 * AS_ST + 3 * BS_ST) * 2; // 56832

__global__ void __launch_bounds__(256, 2)
k_mma(const __half* __restrict__ A, const __half* __restrict__ B,
      int K, int Nc,
      __half* __restrict__ C0, __half* __restrict__ C1, int M)
{
    extern __shared__ __half sm[];
    const int tid = threadIdx.x;
    const int lane = tid & 31, warp = tid >> 5;
    const int wm = warp >> 1, wn = warp & 1;  // 4 x 2 warp grid, 32x64 per warp
    const int blockRow = blockIdx.y * 128;
    const int blockCol = blockIdx.x * 128;

    const int nIter = K >> 5;   // BK = 32

    uint32_t sm_base = (uint32_t)__cvta_generic_to_shared(sm);

    auto prefetch = [&](int it) {
        int st = it % 3;
        int kk = it << 5;
#pragma unroll
        for (int i = 0; i < 2; i++) {
            int idx = tid + i * 256;
            int row = idx >> 2, ch = idx & 3;
            int gr = blockRow + row;
            int ok = (gr < M) ? 16 : 0;
            const __half* srcp = A + (size_t)(ok ? gr : 0) * K + kk + ch * 8;
            uint32_t dstp = sm_base + (st * AS_ST + row * APITCH + ch * 8) * 2;
            CP_ASYNC16(dstp, srcp, ok);
        }
#pragma unroll
        for (int i = 0; i < 2; i++) {
            int idx = tid + i * 256;
            int row = idx >> 4, ch = idx & 15;
            const __half* srcp = B + (size_t)(kk + row) * Nc + blockCol + ch * 8;
            uint32_t dstp = sm_base + (B_OFF + st * BS_ST + row * BPITCH + ch * 8) * 2;
            CP_ASYNC16(dstp, srcp, 16);
        }
    };

    float c[2][8][4];
#pragma unroll
    for (int mt = 0; mt < 2; mt++)
#pragma unroll
        for (int nt = 0; nt < 8; nt++)
#pragma unroll
            for (int q = 0; q < 4; q++) c[mt][nt][q] = 0.f;

    prefetch(0); CP_COMMIT();
    if (nIter > 1) { prefetch(1); CP_COMMIT(); }

#pragma unroll 1
    for (int it = 0; it < nIter; it++) {
        if (it + 2 < nIter) {
            prefetch(it + 2);
            CP_COMMIT();
            CP_WAIT2();
        } else if (it + 1 < nIter) {
            CP_WAIT1();
        } else {
            CP_WAIT0();
        }
        __syncthreads();

        const int st = it % 3;
        const __half* as = sm + st * AS_ST;
        const __half* bs = sm + B_OFF + st * BS_ST;
#pragma unroll
        for (int ks = 0; ks < 2; ks++) {
            uint32_t af[2][4], bfr[4][4];
#pragma unroll
            for (int mt = 0; mt < 2; mt++) {
                int row = wm * 32 + mt * 16 + (lane & 15);
                int col = ks * 16 + (lane >> 4) * 8;
                uint32_t addr = (uint32_t)__cvta_generic_to_shared(&as[row * APITCH + col]);
                asm volatile(
                    "ldmatrix.sync.aligned.m8n8.x4.shared.b16 {%0,%1,%2,%3}, [%4];"
                    : "=r"(af[mt][0]), "=r"(af[mt][1]), "=r"(af[mt][2]), "=r"(af[mt][3])
                    : "r"(addr));
            }
#pragma unroll
            for (int bt = 0; bt < 4; bt++) {
                int row = ks * 16 + (lane & 15);
                int col = wn * 64 + bt * 16 + (lane >> 4) * 8;
                uint32_t addr = (uint32_t)__cvta_generic_to_shared(&bs[row * BPITCH + col]);
                asm volatile(
                    "ldmatrix.sync.aligned.m8n8.x4.trans.shared.b16 {%0,%1,%2,%3}, [%4];"
                    : "=r"(bfr[bt][0]), "=r"(bfr[bt][1]), "=r"(bfr[bt][2]), "=r"(bfr[bt][3])
                    : "r"(addr));
            }
#pragma unroll
            for (int mt = 0; mt < 2; mt++)
#pragma unroll
                for (int nt = 0; nt < 8; nt++) {
                    const uint32_t b0 = bfr[nt >> 1][(nt & 1) * 2];
                    const uint32_t b1 = bfr[nt >> 1][(nt & 1) * 2 + 1];
                    asm volatile(
                        "mma.sync.aligned.m16n8k16.row.col.f32.f16.f16.f32 "
                        "{%0,%1,%2,%3}, {%4,%5,%6,%7}, {%8,%9}, {%0,%1,%2,%3};"
                        : "+f"(c[mt][nt][0]), "+f"(c[mt][nt][1]),
                          "+f"(c[mt][nt][2]), "+f"(c[mt][nt][3])
                        : "r"(af[mt][0]), "r"(af[mt][1]), "r"(af[mt][2]), "r"(af[mt][3]),
                          "r"(b0), "r"(b1));
                }
        }
        __syncthreads();
    }

    // epilogue: fp16 stores
#pragma unroll
    for (int mt = 0; mt < 2; mt++) {
#pragma unroll
        for (int half_ = 0; half_ < 2; half_++) {
            int row = blockRow + wm * 32 + mt * 16 + half_ * 8 + (lane >> 2);
            if (row >= M) continue;
#pragma unroll
            for (int nt = 0; nt < 8; nt++) {
                int gcol = blockCol + wn * 64 + nt * 8 + (lane & 3) * 2;
                __half2 hv = __floats2half2_rn(c[mt][nt][half_ * 2 + 0],
                                               c[mt][nt][half_ * 2 + 1]);
                __half* Cp = (gcol < 256) ? C0 : C1;
                int cc = gcol & 255;
                *(__half2*)&Cp[(size_t)row * 256 + cc] = hv;
            }
        }
    }
}

// ---------------- launch ----------------
extern "C" void kernel_launch(void* const* d_in, const int* in_sizes, int n_in,
                              void* d_out, int out_size) {
    (void)in_sizes; (void)n_in; (void)out_size;
    const float* x   = (const float*)d_in[0];
    const float* x1  = (const float*)d_in[1];
    const int*   ei  = (const int*)d_in[2];
    const int*   src = ei;
    const int*   dst = ei + EE;
    const float* gw0 = (const float*)d_in[3];
    const float* gb0 = (const float*)d_in[4];
    const float* gw1 = (const float*)d_in[5];
    const float* gb1 = (const float*)d_in[6];
    const float* wl0 = (const float*)d_in[7];
    const float* bl0 = (const float*)d_in[8];
    const float* wr0 = (const float*)d_in[9];
    const float* wl1 = (const float*)d_in[10];
    const float* bl1 = (const float*)d_in[11];
    const float* wr1 = (const float*)d_in[12];
    const float* lw  = (const float*)d_in[13];
    const float* lb  = (const float*)d_in[14];
    float* out = (float*)d_out;

    cudaFuncSetAttribute(k_mma, cudaFuncAttributeMaxDynamicSharedMemorySize, SMEM_BYTES);

    __half *p_h1, *p_hcat, *p_h2, *p_Pl, *p_Pr, *p_gw1, *p_w0, *p_w1;
    cudaGetSymbolAddress((void**)&p_h1, d_h1);
    cudaGetSymbolAddress((void**)&p_hcat, d_hcat);
    cudaGetSymbolAddress((void**)&p_h2, d_h2);
    cudaGetSymbolAddress((void**)&p_Pl, d_Pl);
    cudaGetSymbolAddress((void**)&p_Pr, d_Pr);
    cudaGetSymbolAddress((void**)&p_gw1, d_gw1);
    cudaGetSymbolAddress((void**)&p_w0, d_w0);
    cudaGetSymbolAddress((void**)&p_w1, d_w1);

    void *p_cnt, *p_g1;
    cudaGetSymbolAddress(&p_cnt, d_cnt);
    cudaGetSymbolAddress(&p_g1, d_g1);

    // one-time aux stream + events
    static cudaStream_t s_aux = nullptr;
    static cudaEvent_t ev_fork = nullptr, ev_join = nullptr;
    if (s_aux == nullptr) {
        cudaStreamCreateWithFlags(&s_aux, cudaStreamNonBlocking);
        cudaEventCreateWithFlags(&ev_fork, cudaEventDisableTiming);
        cudaEventCreateWithFlags(&ev_join, cudaEventDisableTiming);
    }

    // ---- fork: aux stream does converts + GIN0 + GEMM1 while main builds CSR ----
    cudaEventRecord(ev_fork, 0);
    cudaStreamWaitEvent(s_aux, ev_fork, 0);

    k_cvt_w<<<(HH * HH + 255) / 256, 256, 0, s_aux>>>(gw1, p_gw1, HH * HH, HH, 0);
    k_cvt_w<<<(FH * HH + 255) / 256, 256, 0, s_aux>>>(wl0, p_w0, FH * HH, 512, 0);
    k_cvt_w<<<(FH * HH + 255) / 256, 256, 0, s_aux>>>(wr0, p_w0, FH * HH, 512, 256);
    k_cvt_w<<<(HH * HH + 255) / 256, 256, 0, s_aux>>>(wl1, p_w1, HH * HH, 512, 0);
    k_cvt_w<<<(HH * HH + 255) / 256, 256, 0, s_aux>>>(wr1, p_w1, HH * HH, 512, 256);
    k_split_x<<<(NN * FF + 255) / 256, 256, 0, s_aux>>>(x);
    cudaMemsetAsync(p_g1, 0, NN * sizeof(float), s_aux);
    k_g1_scatter<<<(EE + 255) / 256, 256, 0, s_aux>>>(src, dst, x1);
    k_gin0_act<<<(NN * HH + 255) / 256, 256, 0, s_aux>>>(x1, gw0, gb0);
    k_mma<<<dim3(2, MBLK), 256, SMEM_BYTES, s_aux>>>(p_h1, p_gw1, HH, HH,
                                                     p_Pl, nullptr, NN);
    cudaEventRecord(ev_join, s_aux);

    // main stream: CSR build + degrees
    cudaMemsetAsync(p_cnt, 0, NN * sizeof(int), 0);
    k_count<<<(EE + 255) / 256, 256>>>(dst);
    k_scan1<<<NB_SCAN, 1024>>>();
    k_scan2<<<1, 32>>>();
    k_scan3<<<(NN + 1 + 255) / 256, 256>>>();
    k_fill<<<(EE + 255) / 256, 256>>>(src, dst);

    // ---- join ----
    cudaStreamWaitEvent(0, ev_join, 0);

    // GIN layer 1 combine
    k_comb_gin<<<NCB, 256>>>(p_Pl, gb1);

    // SAGE layer 0
    k_mma<<<dim3(4, MBLK), 256, SMEM_BYTES>>>(p_hcat, p_w0, FH, 512, p_Pl, p_Pr, NN);
    k_comb_sage<<<NCB, 256>>>(p_Pl, p_Pr, bl0, p_h2);

    // SAGE layer 1 + output head
    k_mma<<<dim3(4, MBLK), 256, SMEM_BYTES>>>(p_h2, p_w1, HH, 512, p_Pl, p_Pr, NN);
    k_comb_sage_out<<<NCB, 256>>>(p_Pl, p_Pr, bl1, lw, lb, out);
}